// round 10
// baseline (speedup 1.0000x reference)
#include <cuda_runtime.h>
#include <cuda_fp16.h>
#include <math_constants.h>
#include <cstdint>

// Problem constants
#define BATCH 4
#define SEQ   2048
#define DMODEL 1024
#define NHEAD 16
#define DK    64
#define MROWS (BATCH * SEQ)   // 8192

// ---------------------------------------------------------------------------
// Scratch (static __device__ arrays; no allocations allowed)
// ---------------------------------------------------------------------------
__device__ __half g_qx[MROWS * DMODEL];
__device__ __half g_kx[MROWS * DMODEL];
__device__ __half g_vx[MROWS * DMODEL];
__device__ __half g_wq[DMODEL * DMODEL];
__device__ __half g_wk[DMODEL * DMODEL];
__device__ __half g_wv[DMODEL * DMODEL];
__device__ __half g_wo[DMODEL * DMODEL];
__device__ __half g_Qh[MROWS * DMODEL];
__device__ __half g_Kh[MROWS * DMODEL];
__device__ __half g_Vh[MROWS * DMODEL];
__device__ __half g_Ch[MROWS * DMODEL];

// ---------------------------------------------------------------------------
// Helpers
// ---------------------------------------------------------------------------
__device__ __forceinline__ uint32_t smem_u32(const void* p) {
    uint32_t a;
    asm("{ .reg .u64 t; cvta.to.shared.u64 t, %1; cvt.u32.u64 %0, t; }" : "=r"(a) : "l"(p));
    return a;
}
__device__ __forceinline__ uint32_t pack_half2(float a, float b) {
    __half2 h = __floats2half2_rn(a, b);
    return *reinterpret_cast<uint32_t*>(&h);
}
__device__ __forceinline__ float ex2(float x) {
    float r;
    asm("ex2.approx.f32 %0, %1;" : "=f"(r) : "f"(x));
    return r;
}
__device__ __forceinline__ void cp16(uint32_t dst, const void* src) {
    asm volatile("cp.async.cg.shared.global [%0], [%1], 16;" :: "r"(dst), "l"(src));
}
#define CP_COMMIT() asm volatile("cp.async.commit_group;" ::: "memory")
#define CP_WAIT(n)  asm volatile("cp.async.wait_group %0;" :: "n"(n) : "memory")

__device__ __forceinline__ void ldsm4(uint32_t* r, uint32_t addr) {
    asm volatile("ldmatrix.sync.aligned.m8n8.x4.shared.b16 {%0,%1,%2,%3}, [%4];"
                 : "=r"(r[0]), "=r"(r[1]), "=r"(r[2]), "=r"(r[3]) : "r"(addr));
}
__device__ __forceinline__ void ldsm4t(uint32_t* r, uint32_t addr) {
    asm volatile("ldmatrix.sync.aligned.m8n8.x4.trans.shared.b16 {%0,%1,%2,%3}, [%4];"
                 : "=r"(r[0]), "=r"(r[1]), "=r"(r[2]), "=r"(r[3]) : "r"(addr));
}
__device__ __forceinline__ void mma16816(float* c, const uint32_t* a, uint32_t b0, uint32_t b1) {
    asm volatile(
        "mma.sync.aligned.m16n8k16.row.col.f32.f16.f16.f32 "
        "{%0,%1,%2,%3}, {%4,%5,%6,%7}, {%8,%9}, {%0,%1,%2,%3};"
        : "+f"(c[0]), "+f"(c[1]), "+f"(c[2]), "+f"(c[3])
        : "r"(a[0]), "r"(a[1]), "r"(a[2]), "r"(a[3]), "r"(b0), "r"(b1));
}

// ---------------------------------------------------------------------------
// fp32 -> fp16 conversion (fused over tensors via blockIdx.y)
// ---------------------------------------------------------------------------
struct CvtArgs { const float* s[4]; __half* d[4]; };

__global__ __launch_bounds__(256)
void cvt16m(CvtArgs a, int n4)
{
    const float* s = a.s[blockIdx.y];
    __half* d = a.d[blockIdx.y];
    int i0 = blockIdx.x * 512 + threadIdx.x;
    int i1 = i0 + 256;
    float4 v0 = *(const float4*)(s + (size_t)i0 * 4);
    float4 v1 = *(const float4*)(s + (size_t)i1 * 4);
    uint2 h0, h1;
    h0.x = pack_half2(v0.x, v0.y); h0.y = pack_half2(v0.z, v0.w);
    h1.x = pack_half2(v1.x, v1.y); h1.y = pack_half2(v1.z, v1.w);
    *(uint2*)(d + (size_t)i0 * 4) = h0;
    *(uint2*)(d + (size_t)i1 * 4) = h1;
}

// ---------------------------------------------------------------------------
// FP16 GEMM (NT), 256x128 CTA tile, 64x64 warp tile, BK=32, 3-stage cp.async.
// 256 thr = 8 warps (4 rows x 2 cols). Per kstep: 8 LDSM vs 32 MMA.
// ---------------------------------------------------------------------------
#define BM 256
#define BN 128
#define BK 32
#define KST 40                           // halves per row (80B; 5*16B, gcd(5,8)=1)
#define GA_H (BM * KST)                  // A stage halves (10240)
#define GB_H (BN * KST)                  // B stage halves (5120)
#define GSTG (GA_H + GB_H)               // stage halves (15360)
#define GSM_TOTAL (3 * GSTG * 2)         // bytes (92160)

template<bool F16OUT>
__device__ __forceinline__
void gemm_body(const __half* __restrict__ A, const __half* __restrict__ W,
               const float* __restrict__ bias, void* __restrict__ Cout,
               int N, int K, float alpha, __half* sh, int bx, int by)
{
    const int tid  = threadIdx.x;
    const int lane = tid & 31;
    const int wid  = tid >> 5;
    const int wm   = wid >> 1;   // 0..3 -> rows wm*64
    const int wn   = wid & 1;    // 0..1 -> cols wn*64

    const __half* Ap = A + (size_t)(by * BM) * K;
    const __half* Wp = W + (size_t)(bx * BN) * K;

    float acc[4][8][4];
#pragma unroll
    for (int mt = 0; mt < 4; mt++)
#pragma unroll
        for (int nt = 0; nt < 8; nt++)
#pragma unroll
            for (int r = 0; r < 4; r++) acc[mt][nt][r] = 0.0f;

    const int nslab = K / BK;   // 32
    auto load_tile = [&](int slab, int st) {
        __half* As = sh + st * GSTG;
        __half* Bs = As + GA_H;
        // A: 256x32 halves = 1024 chunks -> 4/thread
#pragma unroll
        for (int i = 0; i < 4; i++) {
            int id = tid + i * 256;
            int r = id >> 2, c = (id & 3) << 3;
            cp16(smem_u32(&As[r * KST + c]), Ap + (size_t)r * K + slab * BK + c);
        }
        // B: 128x32 halves = 512 chunks -> 2/thread
#pragma unroll
        for (int i = 0; i < 2; i++) {
            int id = tid + i * 256;
            int r = id >> 2, c = (id & 3) << 3;
            cp16(smem_u32(&Bs[r * KST + c]), Wp + (size_t)r * K + slab * BK + c);
        }
        CP_COMMIT();
    };

    load_tile(0, 0);
    load_tile(1, 1);
    load_tile(2, 2);

    for (int s = 0; s < nslab; s++) {
        const int st = s % 3;
        if (s + 2 < nslab) CP_WAIT(2);
        else if (s + 1 < nslab) CP_WAIT(1);
        else CP_WAIT(0);
        __syncthreads();

        __half* As = sh + st * GSTG;
        __half* Bs = As + GA_H;
#pragma unroll
        for (int ks = 0; ks < 2; ks++) {
            uint32_t af[4][4], bq[4][4];
#pragma unroll
            for (int mt = 0; mt < 4; mt++) {
                int row = wm * 64 + mt * 16 + (lane & 15);
                int col = ks * 16 + (lane >> 4) * 8;
                ldsm4(af[mt], smem_u32(&As[row * KST + col]));
            }
#pragma unroll
            for (int ntp = 0; ntp < 4; ntp++) {
                int row = wn * 64 + ntp * 16 + (lane & 15);
                int col = ks * 16 + (lane >> 4) * 8;
                ldsm4(bq[ntp], smem_u32(&Bs[row * KST + col]));
            }
#pragma unroll
            for (int mt = 0; mt < 4; mt++)
#pragma unroll
                for (int ntp = 0; ntp < 4; ntp++) {
                    mma16816(acc[mt][ntp * 2],     af[mt], bq[ntp][0], bq[ntp][2]);
                    mma16816(acc[mt][ntp * 2 + 1], af[mt], bq[ntp][1], bq[ntp][3]);
                }
        }
        __syncthreads();
        if (s + 3 < nslab) load_tile(s + 3, st);
    }

    const int rA = lane >> 2, cA = lane & 3;
#pragma unroll
    for (int mt = 0; mt < 4; mt++) {
        int row = by * BM + wm * 64 + mt * 16 + rA;
#pragma unroll
        for (int nt = 0; nt < 8; nt++) {
            int col = bx * BN + wn * 64 + nt * 8 + 2 * cA;
            if (F16OUT) {
                __half* C = (__half*)Cout;
                *(uint32_t*)&C[(size_t)row * N + col] =
                    pack_half2(acc[mt][nt][0] * alpha, acc[mt][nt][1] * alpha);
                *(uint32_t*)&C[(size_t)(row + 8) * N + col] =
                    pack_half2(acc[mt][nt][2] * alpha, acc[mt][nt][3] * alpha);
            } else {
                float* C = (float*)Cout;
                float b0 = bias ? bias[col] : 0.0f;
                float b1 = bias ? bias[col + 1] : 0.0f;
                float2 v0 = { acc[mt][nt][0] + b0, acc[mt][nt][1] + b1 };
                float2 v1 = { acc[mt][nt][2] + b0, acc[mt][nt][3] + b1 };
                *(float2*)&C[(size_t)row * N + col]       = v0;
                *(float2*)&C[(size_t)(row + 8) * N + col] = v1;
            }
        }
    }
}

struct QKVArgs {
    const __half* A[3];
    const __half* W[3];
    __half* C[3];
    float alpha[3];
};

__global__ __launch_bounds__(256)
void gemm_qkv(QKVArgs args)
{
    extern __shared__ __half sh[];
    int z = blockIdx.z;
    gemm_body<true>(args.A[z], args.W[z], nullptr, args.C[z],
                    DMODEL, DMODEL, args.alpha[z], sh, blockIdx.x, blockIdx.y);
}

__global__ __launch_bounds__(256)
void gemm_out(const __half* __restrict__ A, const __half* __restrict__ W,
              const float* __restrict__ bias, float* __restrict__ C)
{
    extern __shared__ __half sh[];
    gemm_body<false>(A, W, bias, C, DMODEL, DMODEL, 1.0f, sh, blockIdx.x, blockIdx.y);
}

// ---------------------------------------------------------------------------
// Flash attention v2-style: P in registers, exp2 softmax, deferred row-sum
// reduction (per-thread partial l, quad-reduced once at the end).
// ---------------------------------------------------------------------------
#define AST 72
#define NKT (SEQ / 64)   // 32

#define ASM_Q  0
#define ASM_K0 (128 * AST)
#define ASM_K1 (ASM_K0 + 64 * AST)
#define ASM_V0 (ASM_K1 + 64 * AST)
#define ASM_V1 (ASM_V0 + 64 * AST)
#define ASM_TOTAL ((ASM_V1 + 64 * AST) * 2)

__global__ __launch_bounds__(256)
void attn_f16(const __half* __restrict__ Q, const __half* __restrict__ Kg,
              const __half* __restrict__ Vg, __half* __restrict__ O)
{
    extern __shared__ __half sh[];
    __half* Qs = sh + ASM_Q;
    __half* Ks[2] = { sh + ASM_K0, sh + ASM_K1 };
    __half* Vs[2] = { sh + ASM_V0, sh + ASM_V1 };

    const int tid  = threadIdx.x;
    const int lane = tid & 31;
    const int wrp  = tid >> 5;
    const int rA   = lane >> 2;
    const int cA   = lane & 3;
    const int b  = blockIdx.z;
    const int h  = blockIdx.y;
    const int q0 = blockIdx.x * 128;

    const __half* Qg = Q  + (size_t)(b * SEQ + q0) * DMODEL + h * DK;
    const __half* Kp = Kg + (size_t)(b * SEQ) * DMODEL + h * DK;
    const __half* Vp = Vg + (size_t)(b * SEQ) * DMODEL + h * DK;

    auto load_kv = [&](int t, int buf) {
#pragma unroll
        for (int i = 0; i < 2; i++) {
            int id = tid + i * 256;
            int r = id >> 3, c = (id & 7) << 3;
            cp16(smem_u32(&Ks[buf][r * AST + c]), Kp + (size_t)(t * 64 + r) * DMODEL + c);
        }
#pragma unroll
        for (int i = 0; i < 2; i++) {
            int id = tid + i * 256;
            int r = id >> 3, c = (id & 7) << 3;
            cp16(smem_u32(&Vs[buf][r * AST + c]), Vp + (size_t)(t * 64 + r) * DMODEL + c);
        }
        CP_COMMIT();
    };

    load_kv(0, 0);

#pragma unroll
    for (int i = 0; i < 4; i++) {
        int id = tid + i * 256;
        int r = id >> 3, c = (id & 7) << 3;
        *(uint4*)&Qs[r * AST + c] = *(const uint4*)(Qg + (size_t)r * DMODEL + c);
    }
    __syncthreads();

    uint32_t qf[4][4];
#pragma unroll
    for (int ks = 0; ks < 4; ks++) {
        int row = wrp * 16 + (lane & 15);
        int col = ks * 16 + (lane >> 4) * 8;
        ldsm4(qf[ks], smem_u32(&Qs[row * AST + col]));
    }

    float of[8][4];
#pragma unroll
    for (int nt = 0; nt < 8; nt++)
#pragma unroll
        for (int r = 0; r < 4; r++) of[nt][r] = 0.0f;
    float m0 = -CUDART_INF_F, m1 = -CUDART_INF_F;
    float l0 = 0.0f, l1 = 0.0f;   // per-thread partial sums (reduced at end)

    for (int t = 0; t < NKT; t++) {
        const int buf = t & 1;
        CP_WAIT(0);
        __syncthreads();
        if (t + 1 < NKT) load_kv(t + 1, buf ^ 1);

        // S = Q @ K^T
        float sc[8][4];
#pragma unroll
        for (int nt = 0; nt < 8; nt++)
#pragma unroll
            for (int r = 0; r < 4; r++) sc[nt][r] = 0.0f;
#pragma unroll
        for (int ks = 0; ks < 4; ks++) {
#pragma unroll
            for (int ntp = 0; ntp < 4; ntp++) {
                uint32_t kb[4];
                int row = ntp * 16 + (lane & 15);
                int col = ks * 16 + (lane >> 4) * 8;
                ldsm4(kb, smem_u32(&Ks[buf][row * AST + col]));
                mma16816(sc[ntp * 2],     qf[ks], kb[0], kb[2]);
                mma16816(sc[ntp * 2 + 1], qf[ks], kb[1], kb[3]);
            }
        }

        // online softmax (exp2 domain); quad max reduce only; sums deferred
        float mx0 = -CUDART_INF_F, mx1 = -CUDART_INF_F;
#pragma unroll
        for (int nt = 0; nt < 8; nt++) {
            mx0 = fmaxf(mx0, fmaxf(sc[nt][0], sc[nt][1]));
            mx1 = fmaxf(mx1, fmaxf(sc[nt][2], sc[nt][3]));
        }
        mx0 = fmaxf(mx0, __shfl_xor_sync(0xffffffffu, mx0, 1));
        mx0 = fmaxf(mx0, __shfl_xor_sync(0xffffffffu, mx0, 2));
        mx1 = fmaxf(mx1, __shfl_xor_sync(0xffffffffu, mx1, 1));
        mx1 = fmaxf(mx1, __shfl_xor_sync(0xffffffffu, mx1, 2));

        float nm0 = fmaxf(m0, mx0), nm1 = fmaxf(m1, mx1);
        float corr0 = ex2(m0 - nm0), corr1 = ex2(m1 - nm1);
        float s0 = 0.0f, s1 = 0.0f;
        uint32_t pf[4][4];
#pragma unroll
        for (int nt = 0; nt < 8; nt++) {
            float p0 = ex2(sc[nt][0] - nm0);
            float p1 = ex2(sc[nt][1] - nm0);
            float p2 = ex2(sc[nt][2] - nm1);
            float p3 = ex2(sc[nt][3] - nm1);
            s0 += p0 + p1; s1 += p2 + p3;
            pf[nt >> 1][(nt & 1) * 2]     = pack_half2(p0, p1);
            pf[nt >> 1][(nt & 1) * 2 + 1] = pack_half2(p2, p3);
        }
        l0 = l0 * corr0 + s0;
        l1 = l1 * corr1 + s1;
        m0 = nm0; m1 = nm1;
#pragma unroll
        for (int nt = 0; nt < 8; nt++) {
            of[nt][0] *= corr0; of[nt][1] *= corr0;
            of[nt][2] *= corr1; of[nt][3] *= corr1;
        }

        // O += P @ V
#pragma unroll
        for (int ks = 0; ks < 4; ks++) {
#pragma unroll
            for (int ntp = 0; ntp < 4; ntp++) {
                uint32_t vb[4];
                int vrow = ks * 16 + (lane & 15);
                int vcol = ntp * 16 + (lane >> 4) * 8;
                ldsm4t(vb, smem_u32(&Vs[buf][vrow * AST + vcol]));
                mma16816(of[ntp * 2],     pf[ks], vb[0], vb[1]);
                mma16816(of[ntp * 2 + 1], pf[ks], vb[2], vb[3]);
            }
        }
    }

    // final row-sum reduction across quad lanes, then normalize + store
    l0 += __shfl_xor_sync(0xffffffffu, l0, 1);
    l0 += __shfl_xor_sync(0xffffffffu, l0, 2);
    l1 += __shfl_xor_sync(0xffffffffu, l1, 1);
    l1 += __shfl_xor_sync(0xffffffffu, l1, 2);
    float inv0 = 1.0f / l0, inv1 = 1.0f / l1;
    __half* Op = O + (size_t)(b * SEQ + q0 + wrp * 16) * DMODEL + h * DK;
#pragma unroll
    for (int nt = 0; nt < 8; nt++) {
        int col = nt * 8 + 2 * cA;
        *(uint32_t*)&Op[(size_t)rA * DMODEL + col] =
            pack_half2(of[nt][0] * inv0, of[nt][1] * inv0);
        *(uint32_t*)&Op[(size_t)(rA + 8) * DMODEL + col] =
            pack_half2(of[nt][2] * inv1, of[nt][3] * inv1);
    }
}

// ---------------------------------------------------------------------------
// Launch
// ---------------------------------------------------------------------------
extern "C" void kernel_launch(void* const* d_in, const int* in_sizes, int n_in,
                              void* d_out, int out_size)
{
    const float* query = (const float*)d_in[0];
    const float* key_  = (const float*)d_in[1];
    const float* value = (const float*)d_in[2];
    const float* w_q   = (const float*)d_in[3];
    const float* w_k   = (const float*)d_in[4];
    const float* w_v   = (const float*)d_in[5];
    const float* w_o   = (const float*)d_in[6];
    const float* b_o   = (const float*)d_in[7];
    float* out = (float*)d_out;

    __half *qx, *kx, *vx, *wq, *wk, *wv, *wo, *Qh, *Kh, *Vh, *Ch;
    cudaGetSymbolAddress((void**)&qx, g_qx);
    cudaGetSymbolAddress((void**)&kx, g_kx);
    cudaGetSymbolAddress((void**)&vx, g_vx);
    cudaGetSymbolAddress((void**)&wq, g_wq);
    cudaGetSymbolAddress((void**)&wk, g_wk);
    cudaGetSymbolAddress((void**)&wv, g_wv);
    cudaGetSymbolAddress((void**)&wo, g_wo);
    cudaGetSymbolAddress((void**)&Qh, g_Qh);
    cudaGetSymbolAddress((void**)&Kh, g_Kh);
    cudaGetSymbolAddress((void**)&Vh, g_Vh);
    cudaGetSymbolAddress((void**)&Ch, g_Ch);

    const int NIN = MROWS * DMODEL / 4;
    const int NW  = DMODEL * DMODEL / 4;
    CvtArgs ia = {{query, key_, value, nullptr}, {qx, kx, vx, nullptr}};
    CvtArgs wa = {{w_q, w_k, w_v, w_o}, {wq, wk, wv, wo}};
    cvt16m<<<dim3(NIN / 512, 3), 256>>>(ia, NIN);
    cvt16m<<<dim3(NW / 512, 4), 256>>>(wa, NW);

    cudaFuncSetAttribute(gemm_qkv, cudaFuncAttributeMaxDynamicSharedMemorySize, GSM_TOTAL);
    cudaFuncSetAttribute(gemm_out, cudaFuncAttributeMaxDynamicSharedMemorySize, GSM_TOTAL);
    cudaFuncSetAttribute(attn_f16, cudaFuncAttributeMaxDynamicSharedMemorySize, ASM_TOTAL);

    QKVArgs qa;
    qa.A[0] = qx; qa.A[1] = kx; qa.A[2] = vx;
    qa.W[0] = wq; qa.W[1] = wk; qa.W[2] = wv;
    qa.C[0] = Qh; qa.C[1] = Kh; qa.C[2] = Vh;
    qa.alpha[0] = 0.125f * 1.44269504088896341f; qa.alpha[1] = 1.0f; qa.alpha[2] = 1.0f;
    gemm_qkv<<<dim3(DMODEL / BN, MROWS / BM, 3), 256, GSM_TOTAL>>>(qa);

    attn_f16<<<dim3(SEQ / 128, NHEAD, BATCH), 256, ASM_TOTAL>>>(Qh, Kh, Vh, Ch);

    gemm_out<<<dim3(DMODEL / BN, MROWS / BM), 256, GSM_TOTAL>>>(Ch, wo, b_o, out);
}

// round 11
// speedup vs baseline: 1.1115x; 1.1115x over previous
#include <cuda_runtime.h>
#include <cuda_fp16.h>
#include <math_constants.h>
#include <cstdint>

// Problem constants
#define BATCH 4
#define SEQ   2048
#define DMODEL 1024
#define NHEAD 16
#define DK    64
#define MROWS (BATCH * SEQ)   // 8192

// ---------------------------------------------------------------------------
// Scratch (static __device__ arrays; no allocations allowed)
// ---------------------------------------------------------------------------
__device__ __half g_qx[MROWS * DMODEL];
__device__ __half g_kx[MROWS * DMODEL];
__device__ __half g_vx[MROWS * DMODEL];
__device__ __half g_wq[DMODEL * DMODEL];
__device__ __half g_wk[DMODEL * DMODEL];
__device__ __half g_wv[DMODEL * DMODEL];
__device__ __half g_wo[DMODEL * DMODEL];
__device__ __half g_Qh[MROWS * DMODEL];
__device__ __half g_Kh[MROWS * DMODEL];
__device__ __half g_Vh[MROWS * DMODEL];
__device__ __half g_Ch[MROWS * DMODEL];

// ---------------------------------------------------------------------------
// Helpers
// ---------------------------------------------------------------------------
__device__ __forceinline__ uint32_t smem_u32(const void* p) {
    uint32_t a;
    asm("{ .reg .u64 t; cvta.to.shared.u64 t, %1; cvt.u32.u64 %0, t; }" : "=r"(a) : "l"(p));
    return a;
}
__device__ __forceinline__ uint32_t pack_half2(float a, float b) {
    __half2 h = __floats2half2_rn(a, b);
    return *reinterpret_cast<uint32_t*>(&h);
}
__device__ __forceinline__ float ex2(float x) {
    float r;
    asm("ex2.approx.f32 %0, %1;" : "=f"(r) : "f"(x));
    return r;
}
__device__ __forceinline__ void cp16(uint32_t dst, const void* src) {
    asm volatile("cp.async.cg.shared.global [%0], [%1], 16;" :: "r"(dst), "l"(src));
}
#define CP_COMMIT() asm volatile("cp.async.commit_group;" ::: "memory")
#define CP_WAIT(n)  asm volatile("cp.async.wait_group %0;" :: "n"(n) : "memory")

__device__ __forceinline__ void ldsm4(uint32_t* r, uint32_t addr) {
    asm volatile("ldmatrix.sync.aligned.m8n8.x4.shared.b16 {%0,%1,%2,%3}, [%4];"
                 : "=r"(r[0]), "=r"(r[1]), "=r"(r[2]), "=r"(r[3]) : "r"(addr));
}
__device__ __forceinline__ void ldsm4t(uint32_t* r, uint32_t addr) {
    asm volatile("ldmatrix.sync.aligned.m8n8.x4.trans.shared.b16 {%0,%1,%2,%3}, [%4];"
                 : "=r"(r[0]), "=r"(r[1]), "=r"(r[2]), "=r"(r[3]) : "r"(addr));
}
__device__ __forceinline__ void mma16816(float* c, const uint32_t* a, uint32_t b0, uint32_t b1) {
    asm volatile(
        "mma.sync.aligned.m16n8k16.row.col.f32.f16.f16.f32 "
        "{%0,%1,%2,%3}, {%4,%5,%6,%7}, {%8,%9}, {%0,%1,%2,%3};"
        : "+f"(c[0]), "+f"(c[1]), "+f"(c[2]), "+f"(c[3])
        : "r"(a[0]), "r"(a[1]), "r"(a[2]), "r"(a[3]), "r"(b0), "r"(b1));
}

// ---------------------------------------------------------------------------
// fp32 -> fp16 conversion (fused over tensors via blockIdx.y)
// ---------------------------------------------------------------------------
struct CvtArgs { const float* s[4]; __half* d[4]; };

__global__ __launch_bounds__(256)
void cvt16m(CvtArgs a, int n4)
{
    const float* s = a.s[blockIdx.y];
    __half* d = a.d[blockIdx.y];
    int i0 = blockIdx.x * 512 + threadIdx.x;
    int i1 = i0 + 256;
    float4 v0 = *(const float4*)(s + (size_t)i0 * 4);
    float4 v1 = *(const float4*)(s + (size_t)i1 * 4);
    uint2 h0, h1;
    h0.x = pack_half2(v0.x, v0.y); h0.y = pack_half2(v0.z, v0.w);
    h1.x = pack_half2(v1.x, v1.y); h1.y = pack_half2(v1.z, v1.w);
    *(uint2*)(d + (size_t)i0 * 4) = h0;
    *(uint2*)(d + (size_t)i1 * 4) = h1;
}

// ---------------------------------------------------------------------------
// FP16 GEMM (NT): exact R8 configuration (known-good local optimum).
// BM=BN=128, BK=64; 256 thr = 8 warps (2x4), warp tile 64x32; 2-stage cp.async.
// ---------------------------------------------------------------------------
#define BM 128
#define BN 128
#define BK 64
#define KST 72
#define GSM_BUF (BM * KST)
#define GSM_TOTAL (4 * GSM_BUF * 2)

template<bool F16OUT>
__device__ __forceinline__
void gemm_body(const __half* __restrict__ A, const __half* __restrict__ W,
               const float* __restrict__ bias, void* __restrict__ Cout,
               int N, int K, float alpha, __half* sh, int bx, int by)
{
    __half* As[2] = { sh, sh + GSM_BUF };
    __half* Bs[2] = { sh + 2 * GSM_BUF, sh + 3 * GSM_BUF };

    const int tid  = threadIdx.x;
    const int lane = tid & 31;
    const int wid  = tid >> 5;
    const int wm   = wid >> 2;
    const int wn   = wid & 3;

    const __half* Ap = A + (size_t)(by * BM) * K;
    const __half* Wp = W + (size_t)(bx * BN) * K;

    float acc[4][4][4];
#pragma unroll
    for (int mt = 0; mt < 4; mt++)
#pragma unroll
        for (int nt = 0; nt < 4; nt++)
#pragma unroll
            for (int r = 0; r < 4; r++) acc[mt][nt][r] = 0.0f;

    const int nslab = K / BK;
    auto load_tile = [&](int slab, int buf) {
#pragma unroll
        for (int i = 0; i < 4; i++) {
            int id = tid + i * 256;
            int r = id >> 3, c = (id & 7) << 3;
            cp16(smem_u32(&As[buf][r * KST + c]), Ap + (size_t)r * K + slab * BK + c);
        }
#pragma unroll
        for (int i = 0; i < 4; i++) {
            int id = tid + i * 256;
            int r = id >> 3, c = (id & 7) << 3;
            cp16(smem_u32(&Bs[buf][r * KST + c]), Wp + (size_t)r * K + slab * BK + c);
        }
        CP_COMMIT();
    };

    load_tile(0, 0);
    load_tile(1, 1);

    for (int s = 0; s < nslab; s++) {
        const int buf = s & 1;
        if (s + 1 < nslab) CP_WAIT(1); else CP_WAIT(0);
        __syncthreads();

#pragma unroll
        for (int ks = 0; ks < 4; ks++) {
            uint32_t af[4][4], bq[2][4];
#pragma unroll
            for (int mt = 0; mt < 4; mt++) {
                int row = wm * 64 + mt * 16 + (lane & 15);
                int col = ks * 16 + (lane >> 4) * 8;
                ldsm4(af[mt], smem_u32(&As[buf][row * KST + col]));
            }
#pragma unroll
            for (int ntp = 0; ntp < 2; ntp++) {
                int row = wn * 32 + ntp * 16 + (lane & 15);
                int col = ks * 16 + (lane >> 4) * 8;
                ldsm4(bq[ntp], smem_u32(&Bs[buf][row * KST + col]));
            }
#pragma unroll
            for (int mt = 0; mt < 4; mt++)
#pragma unroll
                for (int ntp = 0; ntp < 2; ntp++) {
                    mma16816(acc[mt][ntp * 2],     af[mt], bq[ntp][0], bq[ntp][2]);
                    mma16816(acc[mt][ntp * 2 + 1], af[mt], bq[ntp][1], bq[ntp][3]);
                }
        }
        __syncthreads();
        if (s + 2 < nslab) load_tile(s + 2, buf);
    }

    const int rA = lane >> 2, cA = lane & 3;
#pragma unroll
    for (int mt = 0; mt < 4; mt++) {
        int row = by * BM + wm * 64 + mt * 16 + rA;
#pragma unroll
        for (int nt = 0; nt < 4; nt++) {
            int col = bx * BN + wn * 32 + nt * 8 + 2 * cA;
            if (F16OUT) {
                __half* C = (__half*)Cout;
                *(uint32_t*)&C[(size_t)row * N + col] =
                    pack_half2(acc[mt][nt][0] * alpha, acc[mt][nt][1] * alpha);
                *(uint32_t*)&C[(size_t)(row + 8) * N + col] =
                    pack_half2(acc[mt][nt][2] * alpha, acc[mt][nt][3] * alpha);
            } else {
                float* C = (float*)Cout;
                float b0 = bias ? bias[col] : 0.0f;
                float b1 = bias ? bias[col + 1] : 0.0f;
                float2 v0 = { acc[mt][nt][0] + b0, acc[mt][nt][1] + b1 };
                float2 v1 = { acc[mt][nt][2] + b0, acc[mt][nt][3] + b1 };
                *(float2*)&C[(size_t)row * N + col]       = v0;
                *(float2*)&C[(size_t)(row + 8) * N + col] = v1;
            }
        }
    }
}

struct QKVArgs {
    const __half* A[3];
    const __half* W[3];
    __half* C[3];
    float alpha[3];
};

__global__ __launch_bounds__(256)
void gemm_qkv(QKVArgs args)
{
    extern __shared__ __half sh[];
    int z = blockIdx.z;
    gemm_body<true>(args.A[z], args.W[z], nullptr, args.C[z],
                    DMODEL, DMODEL, args.alpha[z], sh, blockIdx.x, blockIdx.y);
}

__global__ __launch_bounds__(256)
void gemm_out(const __half* __restrict__ A, const __half* __restrict__ W,
              const float* __restrict__ bias, float* __restrict__ C)
{
    extern __shared__ __half sh[];
    gemm_body<false>(A, W, bias, C, DMODEL, DMODEL, 1.0f, sh, blockIdx.x, blockIdx.y);
}

// ---------------------------------------------------------------------------
// Flash attention v3: 4 warps x 32 q-rows (two m16 halves, processed
// sequentially through softmax), P in registers, exp2 softmax, deferred
// row-sum. PV pass shares each V fragment across both m-halves (48 LDSM
// per 64 MMA per tile).
// ---------------------------------------------------------------------------
#define AST 72
#define NKT (SEQ / 64)   // 32

#define ASM_Q  0
#define ASM_K0 (128 * AST)
#define ASM_K1 (ASM_K0 + 64 * AST)
#define ASM_V0 (ASM_K1 + 64 * AST)
#define ASM_V1 (ASM_V0 + 64 * AST)
#define ASM_TOTAL ((ASM_V1 + 64 * AST) * 2)   // 55296 bytes

__global__ __launch_bounds__(128)
void attn_f16(const __half* __restrict__ Q, const __half* __restrict__ Kg,
              const __half* __restrict__ Vg, __half* __restrict__ O)
{
    extern __shared__ __half sh[];
    __half* Qs = sh + ASM_Q;
    __half* Ks[2] = { sh + ASM_K0, sh + ASM_K1 };
    __half* Vs[2] = { sh + ASM_V0, sh + ASM_V1 };

    const int tid  = threadIdx.x;
    const int lane = tid & 31;
    const int wrp  = tid >> 5;       // 0..3 -> q rows wrp*32 .. +32
    const int rA   = lane >> 2;
    const int cA   = lane & 3;
    const int b  = blockIdx.z;
    const int h  = blockIdx.y;
    const int q0 = blockIdx.x * 128;

    const __half* Qg = Q  + (size_t)(b * SEQ + q0) * DMODEL + h * DK;
    const __half* Kp = Kg + (size_t)(b * SEQ) * DMODEL + h * DK;
    const __half* Vp = Vg + (size_t)(b * SEQ) * DMODEL + h * DK;

    auto load_kv = [&](int t, int buf) {
        // 64 rows x 64 halves = 512 chunks per matrix; 4 per thread (128 thr)
#pragma unroll
        for (int i = 0; i < 4; i++) {
            int id = tid + i * 128;
            int r = id >> 3, c = (id & 7) << 3;
            cp16(smem_u32(&Ks[buf][r * AST + c]), Kp + (size_t)(t * 64 + r) * DMODEL + c);
        }
#pragma unroll
        for (int i = 0; i < 4; i++) {
            int id = tid + i * 128;
            int r = id >> 3, c = (id & 7) << 3;
            cp16(smem_u32(&Vs[buf][r * AST + c]), Vp + (size_t)(t * 64 + r) * DMODEL + c);
        }
        CP_COMMIT();
    };

    load_kv(0, 0);

    // Q tile: 128 rows x 64 halves = 1024 chunks -> 8 per thread (128 thr)
#pragma unroll
    for (int i = 0; i < 8; i++) {
        int id = tid + i * 128;
        int r = id >> 3, c = (id & 7) << 3;
        *(uint4*)&Qs[r * AST + c] = *(const uint4*)(Qg + (size_t)r * DMODEL + c);
    }
    __syncthreads();

    // Q fragments for both m-halves (persistent)
    uint32_t qf[2][4][4];
#pragma unroll
    for (int mh = 0; mh < 2; mh++)
#pragma unroll
        for (int ks = 0; ks < 4; ks++) {
            int row = wrp * 32 + mh * 16 + (lane & 15);
            int col = ks * 16 + (lane >> 4) * 8;
            ldsm4(qf[mh][ks], smem_u32(&Qs[row * AST + col]));
        }

    float of[2][8][4];
#pragma unroll
    for (int mh = 0; mh < 2; mh++)
#pragma unroll
        for (int nt = 0; nt < 8; nt++)
#pragma unroll
            for (int r = 0; r < 4; r++) of[mh][nt][r] = 0.0f;
    float mrun[2][2] = {{-CUDART_INF_F, -CUDART_INF_F}, {-CUDART_INF_F, -CUDART_INF_F}};
    float lrun[2][2] = {{0.0f, 0.0f}, {0.0f, 0.0f}};

    for (int t = 0; t < NKT; t++) {
        const int buf = t & 1;
        CP_WAIT(0);
        __syncthreads();
        if (t + 1 < NKT) load_kv(t + 1, buf ^ 1);

        uint32_t pf[2][4][4];
#pragma unroll
        for (int mh = 0; mh < 2; mh++) {
            // S(mh) = Q(mh) @ K^T
            float sc[8][4];
#pragma unroll
            for (int nt = 0; nt < 8; nt++)
#pragma unroll
                for (int r = 0; r < 4; r++) sc[nt][r] = 0.0f;
#pragma unroll
            for (int ks = 0; ks < 4; ks++) {
#pragma unroll
                for (int ntp = 0; ntp < 4; ntp++) {
                    uint32_t kb[4];
                    int row = ntp * 16 + (lane & 15);
                    int col = ks * 16 + (lane >> 4) * 8;
                    ldsm4(kb, smem_u32(&Ks[buf][row * AST + col]));
                    mma16816(sc[ntp * 2],     qf[mh][ks], kb[0], kb[2]);
                    mma16816(sc[ntp * 2 + 1], qf[mh][ks], kb[1], kb[3]);
                }
            }

            // online softmax (exp2 domain), deferred row-sums
            float mx0 = -CUDART_INF_F, mx1 = -CUDART_INF_F;
#pragma unroll
            for (int nt = 0; nt < 8; nt++) {
                mx0 = fmaxf(mx0, fmaxf(sc[nt][0], sc[nt][1]));
                mx1 = fmaxf(mx1, fmaxf(sc[nt][2], sc[nt][3]));
            }
            mx0 = fmaxf(mx0, __shfl_xor_sync(0xffffffffu, mx0, 1));
            mx0 = fmaxf(mx0, __shfl_xor_sync(0xffffffffu, mx0, 2));
            mx1 = fmaxf(mx1, __shfl_xor_sync(0xffffffffu, mx1, 1));
            mx1 = fmaxf(mx1, __shfl_xor_sync(0xffffffffu, mx1, 2));

            float nm0 = fmaxf(mrun[mh][0], mx0), nm1 = fmaxf(mrun[mh][1], mx1);
            float corr0 = ex2(mrun[mh][0] - nm0), corr1 = ex2(mrun[mh][1] - nm1);
            float s0 = 0.0f, s1 = 0.0f;
#pragma unroll
            for (int nt = 0; nt < 8; nt++) {
                float p0 = ex2(sc[nt][0] - nm0);
                float p1 = ex2(sc[nt][1] - nm0);
                float p2 = ex2(sc[nt][2] - nm1);
                float p3 = ex2(sc[nt][3] - nm1);
                s0 += p0 + p1; s1 += p2 + p3;
                pf[mh][nt >> 1][(nt & 1) * 2]     = pack_half2(p0, p1);
                pf[mh][nt >> 1][(nt & 1) * 2 + 1] = pack_half2(p2, p3);
            }
            lrun[mh][0] = lrun[mh][0] * corr0 + s0;
            lrun[mh][1] = lrun[mh][1] * corr1 + s1;
            mrun[mh][0] = nm0; mrun[mh][1] = nm1;
#pragma unroll
            for (int nt = 0; nt < 8; nt++) {
                of[mh][nt][0] *= corr0; of[mh][nt][1] *= corr0;
                of[mh][nt][2] *= corr1; of[mh][nt][3] *= corr1;
            }
        }

        // O += P @ V — each V fragment feeds both m-halves
#pragma unroll
        for (int ks = 0; ks < 4; ks++) {
#pragma unroll
            for (int ntp = 0; ntp < 4; ntp++) {
                uint32_t vb[4];
                int vrow = ks * 16 + (lane & 15);
                int vcol = ntp * 16 + (lane >> 4) * 8;
                ldsm4t(vb, smem_u32(&Vs[buf][vrow * AST + vcol]));
                mma16816(of[0][ntp * 2],     pf[0][ks], vb[0], vb[1]);
                mma16816(of[0][ntp * 2 + 1], pf[0][ks], vb[2], vb[3]);
                mma16816(of[1][ntp * 2],     pf[1][ks], vb[0], vb[1]);
                mma16816(of[1][ntp * 2 + 1], pf[1][ks], vb[2], vb[3]);
            }
        }
    }

    // final row-sum reductions, normalize, store
#pragma unroll
    for (int mh = 0; mh < 2; mh++) {
        float l0 = lrun[mh][0], l1 = lrun[mh][1];
        l0 += __shfl_xor_sync(0xffffffffu, l0, 1);
        l0 += __shfl_xor_sync(0xffffffffu, l0, 2);
        l1 += __shfl_xor_sync(0xffffffffu, l1, 1);
        l1 += __shfl_xor_sync(0xffffffffu, l1, 2);
        float inv0 = 1.0f / l0, inv1 = 1.0f / l1;
        __half* Op = O + (size_t)(b * SEQ + q0 + wrp * 32 + mh * 16) * DMODEL + h * DK;
#pragma unroll
        for (int nt = 0; nt < 8; nt++) {
            int col = nt * 8 + 2 * cA;
            *(uint32_t*)&Op[(size_t)rA * DMODEL + col] =
                pack_half2(of[mh][nt][0] * inv0, of[mh][nt][1] * inv0);
            *(uint32_t*)&Op[(size_t)(rA + 8) * DMODEL + col] =
                pack_half2(of[mh][nt][2] * inv1, of[mh][nt][3] * inv1);
        }
    }
}

// ---------------------------------------------------------------------------
// Launch
// ---------------------------------------------------------------------------
extern "C" void kernel_launch(void* const* d_in, const int* in_sizes, int n_in,
                              void* d_out, int out_size)
{
    const float* query = (const float*)d_in[0];
    const float* key_  = (const float*)d_in[1];
    const float* value = (const float*)d_in[2];
    const float* w_q   = (const float*)d_in[3];
    const float* w_k   = (const float*)d_in[4];
    const float* w_v   = (const float*)d_in[5];
    const float* w_o   = (const float*)d_in[6];
    const float* b_o   = (const float*)d_in[7];
    float* out = (float*)d_out;

    __half *qx, *kx, *vx, *wq, *wk, *wv, *wo, *Qh, *Kh, *Vh, *Ch;
    cudaGetSymbolAddress((void**)&qx, g_qx);
    cudaGetSymbolAddress((void**)&kx, g_kx);
    cudaGetSymbolAddress((void**)&vx, g_vx);
    cudaGetSymbolAddress((void**)&wq, g_wq);
    cudaGetSymbolAddress((void**)&wk, g_wk);
    cudaGetSymbolAddress((void**)&wv, g_wv);
    cudaGetSymbolAddress((void**)&wo, g_wo);
    cudaGetSymbolAddress((void**)&Qh, g_Qh);
    cudaGetSymbolAddress((void**)&Kh, g_Kh);
    cudaGetSymbolAddress((void**)&Vh, g_Vh);
    cudaGetSymbolAddress((void**)&Ch, g_Ch);

    const int NIN = MROWS * DMODEL / 4;
    const int NW  = DMODEL * DMODEL / 4;
    CvtArgs ia = {{query, key_, value, nullptr}, {qx, kx, vx, nullptr}};
    CvtArgs wa = {{w_q, w_k, w_v, w_o}, {wq, wk, wv, wo}};
    cvt16m<<<dim3(NIN / 512, 3), 256>>>(ia, NIN);
    cvt16m<<<dim3(NW / 512, 4), 256>>>(wa, NW);

    cudaFuncSetAttribute(gemm_qkv, cudaFuncAttributeMaxDynamicSharedMemorySize, GSM_TOTAL);
    cudaFuncSetAttribute(gemm_out, cudaFuncAttributeMaxDynamicSharedMemorySize, GSM_TOTAL);
    cudaFuncSetAttribute(attn_f16, cudaFuncAttributeMaxDynamicSharedMemorySize, ASM_TOTAL);

    QKVArgs qa;
    qa.A[0] = qx; qa.A[1] = kx; qa.A[2] = vx;
    qa.W[0] = wq; qa.W[1] = wk; qa.W[2] = wv;
    qa.C[0] = Qh; qa.C[1] = Kh; qa.C[2] = Vh;
    qa.alpha[0] = 0.125f * 1.44269504088896341f; qa.alpha[1] = 1.0f; qa.alpha[2] = 1.0f;
    gemm_qkv<<<dim3(DMODEL / BN, MROWS / BM, 3), 256, GSM_TOTAL>>>(qa);

    attn_f16<<<dim3(SEQ / 128, NHEAD, BATCH), 128, ASM_TOTAL>>>(Qh, Kh, Vh, Ch);

    gemm_out<<<dim3(DMODEL / BN, MROWS / BM), 256, GSM_TOTAL>>>(Ch, wo, b_o, out);
}

// round 12
// speedup vs baseline: 1.1126x; 1.0010x over previous
#include <cuda_runtime.h>
#include <cuda_fp16.h>
#include <math_constants.h>
#include <cstdint>

// Problem constants
#define BATCH 4
#define SEQ   2048
#define DMODEL 1024
#define NHEAD 16
#define DK    64
#define MROWS (BATCH * SEQ)   // 8192

// ---------------------------------------------------------------------------
// Scratch (static __device__ arrays; no allocations allowed)
// ---------------------------------------------------------------------------
__device__ __half g_qx[MROWS * DMODEL];
__device__ __half g_kx[MROWS * DMODEL];
__device__ __half g_vx[MROWS * DMODEL];
__device__ __half g_wq[DMODEL * DMODEL];
__device__ __half g_wk[DMODEL * DMODEL];
__device__ __half g_wv[DMODEL * DMODEL];
__device__ __half g_wo[DMODEL * DMODEL];
__device__ __half g_Qh[MROWS * DMODEL];
__device__ __half g_Kh[MROWS * DMODEL];
__device__ __half g_Vh[MROWS * DMODEL];
__device__ __half g_Ch[MROWS * DMODEL];

// ---------------------------------------------------------------------------
// Helpers
// ---------------------------------------------------------------------------
__device__ __forceinline__ uint32_t smem_u32(const void* p) {
    uint32_t a;
    asm("{ .reg .u64 t; cvta.to.shared.u64 t, %1; cvt.u32.u64 %0, t; }" : "=r"(a) : "l"(p));
    return a;
}
__device__ __forceinline__ uint32_t pack_half2(float a, float b) {
    __half2 h = __floats2half2_rn(a, b);
    return *reinterpret_cast<uint32_t*>(&h);
}
__device__ __forceinline__ float ex2(float x) {
    float r;
    asm("ex2.approx.f32 %0, %1;" : "=f"(r) : "f"(x));
    return r;
}
__device__ __forceinline__ void cp16(uint32_t dst, const void* src) {
    asm volatile("cp.async.cg.shared.global [%0], [%1], 16;" :: "r"(dst), "l"(src));
}
#define CP_COMMIT() asm volatile("cp.async.commit_group;" ::: "memory")
#define CP_WAIT(n)  asm volatile("cp.async.wait_group %0;" :: "n"(n) : "memory")

__device__ __forceinline__ void ldsm4(uint32_t* r, uint32_t addr) {
    asm volatile("ldmatrix.sync.aligned.m8n8.x4.shared.b16 {%0,%1,%2,%3}, [%4];"
                 : "=r"(r[0]), "=r"(r[1]), "=r"(r[2]), "=r"(r[3]) : "r"(addr));
}
__device__ __forceinline__ void ldsm4t(uint32_t* r, uint32_t addr) {
    asm volatile("ldmatrix.sync.aligned.m8n8.x4.trans.shared.b16 {%0,%1,%2,%3}, [%4];"
                 : "=r"(r[0]), "=r"(r[1]), "=r"(r[2]), "=r"(r[3]) : "r"(addr));
}
__device__ __forceinline__ void mma16816(float* c, const uint32_t* a, uint32_t b0, uint32_t b1) {
    asm volatile(
        "mma.sync.aligned.m16n8k16.row.col.f32.f16.f16.f32 "
        "{%0,%1,%2,%3}, {%4,%5,%6,%7}, {%8,%9}, {%0,%1,%2,%3};"
        : "+f"(c[0]), "+f"(c[1]), "+f"(c[2]), "+f"(c[3])
        : "r"(a[0]), "r"(a[1]), "r"(a[2]), "r"(a[3]), "r"(b0), "r"(b1));
}

// ---------------------------------------------------------------------------
// fp32 -> fp16 conversion (fused over tensors via blockIdx.y)
// ---------------------------------------------------------------------------
struct CvtArgs { const float* s[4]; __half* d[4]; };

__global__ __launch_bounds__(256)
void cvt16m(CvtArgs a, int n4)
{
    const float* s = a.s[blockIdx.y];
    __half* d = a.d[blockIdx.y];
    int i0 = blockIdx.x * 512 + threadIdx.x;
    int i1 = i0 + 256;
    float4 v0 = *(const float4*)(s + (size_t)i0 * 4);
    float4 v1 = *(const float4*)(s + (size_t)i1 * 4);
    uint2 h0, h1;
    h0.x = pack_half2(v0.x, v0.y); h0.y = pack_half2(v0.z, v0.w);
    h1.x = pack_half2(v1.x, v1.y); h1.y = pack_half2(v1.z, v1.w);
    *(uint2*)(d + (size_t)i0 * 4) = h0;
    *(uint2*)(d + (size_t)i1 * 4) = h1;
}

// ---------------------------------------------------------------------------
// FP16 GEMM (NT): exact R8 configuration (known-good local optimum).
// ---------------------------------------------------------------------------
#define BM 128
#define BN 128
#define BK 64
#define KST 72
#define GSM_BUF (BM * KST)
#define GSM_TOTAL (4 * GSM_BUF * 2)

template<bool F16OUT>
__device__ __forceinline__
void gemm_body(const __half* __restrict__ A, const __half* __restrict__ W,
               const float* __restrict__ bias, void* __restrict__ Cout,
               int N, int K, float alpha, __half* sh, int bx, int by)
{
    __half* As[2] = { sh, sh + GSM_BUF };
    __half* Bs[2] = { sh + 2 * GSM_BUF, sh + 3 * GSM_BUF };

    const int tid  = threadIdx.x;
    const int lane = tid & 31;
    const int wid  = tid >> 5;
    const int wm   = wid >> 2;
    const int wn   = wid & 3;

    const __half* Ap = A + (size_t)(by * BM) * K;
    const __half* Wp = W + (size_t)(bx * BN) * K;

    float acc[4][4][4];
#pragma unroll
    for (int mt = 0; mt < 4; mt++)
#pragma unroll
        for (int nt = 0; nt < 4; nt++)
#pragma unroll
            for (int r = 0; r < 4; r++) acc[mt][nt][r] = 0.0f;

    const int nslab = K / BK;
    auto load_tile = [&](int slab, int buf) {
#pragma unroll
        for (int i = 0; i < 4; i++) {
            int id = tid + i * 256;
            int r = id >> 3, c = (id & 7) << 3;
            cp16(smem_u32(&As[buf][r * KST + c]), Ap + (size_t)r * K + slab * BK + c);
        }
#pragma unroll
        for (int i = 0; i < 4; i++) {
            int id = tid + i * 256;
            int r = id >> 3, c = (id & 7) << 3;
            cp16(smem_u32(&Bs[buf][r * KST + c]), Wp + (size_t)r * K + slab * BK + c);
        }
        CP_COMMIT();
    };

    load_tile(0, 0);
    load_tile(1, 1);

    for (int s = 0; s < nslab; s++) {
        const int buf = s & 1;
        if (s + 1 < nslab) CP_WAIT(1); else CP_WAIT(0);
        __syncthreads();

#pragma unroll
        for (int ks = 0; ks < 4; ks++) {
            uint32_t af[4][4], bq[2][4];
#pragma unroll
            for (int mt = 0; mt < 4; mt++) {
                int row = wm * 64 + mt * 16 + (lane & 15);
                int col = ks * 16 + (lane >> 4) * 8;
                ldsm4(af[mt], smem_u32(&As[buf][row * KST + col]));
            }
#pragma unroll
            for (int ntp = 0; ntp < 2; ntp++) {
                int row = wn * 32 + ntp * 16 + (lane & 15);
                int col = ks * 16 + (lane >> 4) * 8;
                ldsm4(bq[ntp], smem_u32(&Bs[buf][row * KST + col]));
            }
#pragma unroll
            for (int mt = 0; mt < 4; mt++)
#pragma unroll
                for (int ntp = 0; ntp < 2; ntp++) {
                    mma16816(acc[mt][ntp * 2],     af[mt], bq[ntp][0], bq[ntp][2]);
                    mma16816(acc[mt][ntp * 2 + 1], af[mt], bq[ntp][1], bq[ntp][3]);
                }
        }
        __syncthreads();
        if (s + 2 < nslab) load_tile(s + 2, buf);
    }

    const int rA = lane >> 2, cA = lane & 3;
#pragma unroll
    for (int mt = 0; mt < 4; mt++) {
        int row = by * BM + wm * 64 + mt * 16 + rA;
#pragma unroll
        for (int nt = 0; nt < 4; nt++) {
            int col = bx * BN + wn * 32 + nt * 8 + 2 * cA;
            if (F16OUT) {
                __half* C = (__half*)Cout;
                *(uint32_t*)&C[(size_t)row * N + col] =
                    pack_half2(acc[mt][nt][0] * alpha, acc[mt][nt][1] * alpha);
                *(uint32_t*)&C[(size_t)(row + 8) * N + col] =
                    pack_half2(acc[mt][nt][2] * alpha, acc[mt][nt][3] * alpha);
            } else {
                float* C = (float*)Cout;
                float b0 = bias ? bias[col] : 0.0f;
                float b1 = bias ? bias[col + 1] : 0.0f;
                float2 v0 = { acc[mt][nt][0] + b0, acc[mt][nt][1] + b1 };
                float2 v1 = { acc[mt][nt][2] + b0, acc[mt][nt][3] + b1 };
                *(float2*)&C[(size_t)row * N + col]       = v0;
                *(float2*)&C[(size_t)(row + 8) * N + col] = v1;
            }
        }
    }
}

struct QKVArgs {
    const __half* A[3];
    const __half* W[3];
    __half* C[3];
    float alpha[3];
};

__global__ __launch_bounds__(256)
void gemm_qkv(QKVArgs args)
{
    extern __shared__ __half sh[];
    int z = blockIdx.z;
    gemm_body<true>(args.A[z], args.W[z], nullptr, args.C[z],
                    DMODEL, DMODEL, args.alpha[z], sh, blockIdx.x, blockIdx.y);
}

__global__ __launch_bounds__(256)
void gemm_out(const __half* __restrict__ A, const __half* __restrict__ W,
              const float* __restrict__ bias, float* __restrict__ C)
{
    extern __shared__ __half sh[];
    gemm_body<false>(A, W, bias, C, DMODEL, DMODEL, 1.0f, sh, blockIdx.x, blockIdx.y);
}

// ---------------------------------------------------------------------------
// Flash attention v3.1: 4 warps x 32 q-rows. BOTH K and V fragments shared
// across the two m16 halves (32 LDSM per 64 MMA per tile). P in registers,
// exp2 softmax, deferred row-sum.
// ---------------------------------------------------------------------------
#define AST 72
#define NKT (SEQ / 64)   // 32

#define ASM_Q  0
#define ASM_K0 (128 * AST)
#define ASM_K1 (ASM_K0 + 64 * AST)
#define ASM_V0 (ASM_K1 + 64 * AST)
#define ASM_V1 (ASM_V0 + 64 * AST)
#define ASM_TOTAL ((ASM_V1 + 64 * AST) * 2)   // 55296 bytes

__global__ __launch_bounds__(128)
void attn_f16(const __half* __restrict__ Q, const __half* __restrict__ Kg,
              const __half* __restrict__ Vg, __half* __restrict__ O)
{
    extern __shared__ __half sh[];
    __half* Qs = sh + ASM_Q;
    __half* Ks[2] = { sh + ASM_K0, sh + ASM_K1 };
    __half* Vs[2] = { sh + ASM_V0, sh + ASM_V1 };

    const int tid  = threadIdx.x;
    const int lane = tid & 31;
    const int wrp  = tid >> 5;       // 0..3 -> q rows wrp*32 .. +32
    const int rA   = lane >> 2;
    const int cA   = lane & 3;
    const int b  = blockIdx.z;
    const int h  = blockIdx.y;
    const int q0 = blockIdx.x * 128;

    const __half* Qg = Q  + (size_t)(b * SEQ + q0) * DMODEL + h * DK;
    const __half* Kp = Kg + (size_t)(b * SEQ) * DMODEL + h * DK;
    const __half* Vp = Vg + (size_t)(b * SEQ) * DMODEL + h * DK;

    auto load_kv = [&](int t, int buf) {
#pragma unroll
        for (int i = 0; i < 4; i++) {
            int id = tid + i * 128;
            int r = id >> 3, c = (id & 7) << 3;
            cp16(smem_u32(&Ks[buf][r * AST + c]), Kp + (size_t)(t * 64 + r) * DMODEL + c);
        }
#pragma unroll
        for (int i = 0; i < 4; i++) {
            int id = tid + i * 128;
            int r = id >> 3, c = (id & 7) << 3;
            cp16(smem_u32(&Vs[buf][r * AST + c]), Vp + (size_t)(t * 64 + r) * DMODEL + c);
        }
        CP_COMMIT();
    };

    load_kv(0, 0);

    // Q tile: 128 rows x 64 halves = 1024 chunks -> 8 per thread (128 thr)
#pragma unroll
    for (int i = 0; i < 8; i++) {
        int id = tid + i * 128;
        int r = id >> 3, c = (id & 7) << 3;
        *(uint4*)&Qs[r * AST + c] = *(const uint4*)(Qg + (size_t)r * DMODEL + c);
    }
    __syncthreads();

    // Q fragments for both m-halves (persistent)
    uint32_t qf[2][4][4];
#pragma unroll
    for (int mh = 0; mh < 2; mh++)
#pragma unroll
        for (int ks = 0; ks < 4; ks++) {
            int row = wrp * 32 + mh * 16 + (lane & 15);
            int col = ks * 16 + (lane >> 4) * 8;
            ldsm4(qf[mh][ks], smem_u32(&Qs[row * AST + col]));
        }

    float of[2][8][4];
#pragma unroll
    for (int mh = 0; mh < 2; mh++)
#pragma unroll
        for (int nt = 0; nt < 8; nt++)
#pragma unroll
            for (int r = 0; r < 4; r++) of[mh][nt][r] = 0.0f;
    float mrun[2][2] = {{-CUDART_INF_F, -CUDART_INF_F}, {-CUDART_INF_F, -CUDART_INF_F}};
    float lrun[2][2] = {{0.0f, 0.0f}, {0.0f, 0.0f}};

    for (int t = 0; t < NKT; t++) {
        const int buf = t & 1;
        CP_WAIT(0);
        __syncthreads();
        if (t + 1 < NKT) load_kv(t + 1, buf ^ 1);

        // S = Q @ K^T for BOTH m-halves, each K fragment loaded once
        float sc[2][8][4];
#pragma unroll
        for (int mh = 0; mh < 2; mh++)
#pragma unroll
            for (int nt = 0; nt < 8; nt++)
#pragma unroll
                for (int r = 0; r < 4; r++) sc[mh][nt][r] = 0.0f;
#pragma unroll
        for (int ks = 0; ks < 4; ks++) {
#pragma unroll
            for (int ntp = 0; ntp < 4; ntp++) {
                uint32_t kb[4];
                int row = ntp * 16 + (lane & 15);
                int col = ks * 16 + (lane >> 4) * 8;
                ldsm4(kb, smem_u32(&Ks[buf][row * AST + col]));
                mma16816(sc[0][ntp * 2],     qf[0][ks], kb[0], kb[2]);
                mma16816(sc[0][ntp * 2 + 1], qf[0][ks], kb[1], kb[3]);
                mma16816(sc[1][ntp * 2],     qf[1][ks], kb[0], kb[2]);
                mma16816(sc[1][ntp * 2 + 1], qf[1][ks], kb[1], kb[3]);
            }
        }

        // online softmax per half (exp2 domain), deferred row-sums
        uint32_t pf[2][4][4];
#pragma unroll
        for (int mh = 0; mh < 2; mh++) {
            float mx0 = -CUDART_INF_F, mx1 = -CUDART_INF_F;
#pragma unroll
            for (int nt = 0; nt < 8; nt++) {
                mx0 = fmaxf(mx0, fmaxf(sc[mh][nt][0], sc[mh][nt][1]));
                mx1 = fmaxf(mx1, fmaxf(sc[mh][nt][2], sc[mh][nt][3]));
            }
            mx0 = fmaxf(mx0, __shfl_xor_sync(0xffffffffu, mx0, 1));
            mx0 = fmaxf(mx0, __shfl_xor_sync(0xffffffffu, mx0, 2));
            mx1 = fmaxf(mx1, __shfl_xor_sync(0xffffffffu, mx1, 1));
            mx1 = fmaxf(mx1, __shfl_xor_sync(0xffffffffu, mx1, 2));

            float nm0 = fmaxf(mrun[mh][0], mx0), nm1 = fmaxf(mrun[mh][1], mx1);
            float corr0 = ex2(mrun[mh][0] - nm0), corr1 = ex2(mrun[mh][1] - nm1);
            float s0 = 0.0f, s1 = 0.0f;
#pragma unroll
            for (int nt = 0; nt < 8; nt++) {
                float p0 = ex2(sc[mh][nt][0] - nm0);
                float p1 = ex2(sc[mh][nt][1] - nm0);
                float p2 = ex2(sc[mh][nt][2] - nm1);
                float p3 = ex2(sc[mh][nt][3] - nm1);
                s0 += p0 + p1; s1 += p2 + p3;
                pf[mh][nt >> 1][(nt & 1) * 2]     = pack_half2(p0, p1);
                pf[mh][nt >> 1][(nt & 1) * 2 + 1] = pack_half2(p2, p3);
            }
            lrun[mh][0] = lrun[mh][0] * corr0 + s0;
            lrun[mh][1] = lrun[mh][1] * corr1 + s1;
            mrun[mh][0] = nm0; mrun[mh][1] = nm1;
#pragma unroll
            for (int nt = 0; nt < 8; nt++) {
                of[mh][nt][0] *= corr0; of[mh][nt][1] *= corr0;
                of[mh][nt][2] *= corr1; of[mh][nt][3] *= corr1;
            }
        }

        // O += P @ V — each V fragment feeds both m-halves
#pragma unroll
        for (int ks = 0; ks < 4; ks++) {
#pragma unroll
            for (int ntp = 0; ntp < 4; ntp++) {
                uint32_t vb[4];
                int vrow = ks * 16 + (lane & 15);
                int vcol = ntp * 16 + (lane >> 4) * 8;
                ldsm4t(vb, smem_u32(&Vs[buf][vrow * AST + vcol]));
                mma16816(of[0][ntp * 2],     pf[0][ks], vb[0], vb[1]);
                mma16816(of[0][ntp * 2 + 1], pf[0][ks], vb[2], vb[3]);
                mma16816(of[1][ntp * 2],     pf[1][ks], vb[0], vb[1]);
                mma16816(of[1][ntp * 2 + 1], pf[1][ks], vb[2], vb[3]);
            }
        }
    }

    // final row-sum reductions, normalize, store
#pragma unroll
    for (int mh = 0; mh < 2; mh++) {
        float l0 = lrun[mh][0], l1 = lrun[mh][1];
        l0 += __shfl_xor_sync(0xffffffffu, l0, 1);
        l0 += __shfl_xor_sync(0xffffffffu, l0, 2);
        l1 += __shfl_xor_sync(0xffffffffu, l1, 1);
        l1 += __shfl_xor_sync(0xffffffffu, l1, 2);
        float inv0 = 1.0f / l0, inv1 = 1.0f / l1;
        __half* Op = O + (size_t)(b * SEQ + q0 + wrp * 32 + mh * 16) * DMODEL + h * DK;
#pragma unroll
        for (int nt = 0; nt < 8; nt++) {
            int col = nt * 8 + 2 * cA;
            *(uint32_t*)&Op[(size_t)rA * DMODEL + col] =
                pack_half2(of[mh][nt][0] * inv0, of[mh][nt][1] * inv0);
            *(uint32_t*)&Op[(size_t)(rA + 8) * DMODEL + col] =
                pack_half2(of[mh][nt][2] * inv1, of[mh][nt][3] * inv1);
        }
    }
}

// ---------------------------------------------------------------------------
// Launch
// ---------------------------------------------------------------------------
extern "C" void kernel_launch(void* const* d_in, const int* in_sizes, int n_in,
                              void* d_out, int out_size)
{
    const float* query = (const float*)d_in[0];
    const float* key_  = (const float*)d_in[1];
    const float* value = (const float*)d_in[2];
    const float* w_q   = (const float*)d_in[3];
    const float* w_k   = (const float*)d_in[4];
    const float* w_v   = (const float*)d_in[5];
    const float* w_o   = (const float*)d_in[6];
    const float* b_o   = (const float*)d_in[7];
    float* out = (float*)d_out;

    __half *qx, *kx, *vx, *wq, *wk, *wv, *wo, *Qh, *Kh, *Vh, *Ch;
    cudaGetSymbolAddress((void**)&qx, g_qx);
    cudaGetSymbolAddress((void**)&kx, g_kx);
    cudaGetSymbolAddress((void**)&vx, g_vx);
    cudaGetSymbolAddress((void**)&wq, g_wq);
    cudaGetSymbolAddress((void**)&wk, g_wk);
    cudaGetSymbolAddress((void**)&wv, g_wv);
    cudaGetSymbolAddress((void**)&wo, g_wo);
    cudaGetSymbolAddress((void**)&Qh, g_Qh);
    cudaGetSymbolAddress((void**)&Kh, g_Kh);
    cudaGetSymbolAddress((void**)&Vh, g_Vh);
    cudaGetSymbolAddress((void**)&Ch, g_Ch);

    const int NIN = MROWS * DMODEL / 4;
    const int NW  = DMODEL * DMODEL / 4;
    CvtArgs ia = {{query, key_, value, nullptr}, {qx, kx, vx, nullptr}};
    CvtArgs wa = {{w_q, w_k, w_v, w_o}, {wq, wk, wv, wo}};
    cvt16m<<<dim3(NIN / 512, 3), 256>>>(ia, NIN);
    cvt16m<<<dim3(NW / 512, 4), 256>>>(wa, NW);

    cudaFuncSetAttribute(gemm_qkv, cudaFuncAttributeMaxDynamicSharedMemorySize, GSM_TOTAL);
    cudaFuncSetAttribute(gemm_out, cudaFuncAttributeMaxDynamicSharedMemorySize, GSM_TOTAL);
    cudaFuncSetAttribute(attn_f16, cudaFuncAttributeMaxDynamicSharedMemorySize, ASM_TOTAL);

    QKVArgs qa;
    qa.A[0] = qx; qa.A[1] = kx; qa.A[2] = vx;
    qa.W[0] = wq; qa.W[1] = wk; qa.W[2] = wv;
    qa.C[0] = Qh; qa.C[1] = Kh; qa.C[2] = Vh;
    qa.alpha[0] = 0.125f * 1.44269504088896341f; qa.alpha[1] = 1.0f; qa.alpha[2] = 1.0f;
    gemm_qkv<<<dim3(DMODEL / BN, MROWS / BM, 3), 256, GSM_TOTAL>>>(qa);

    attn_f16<<<dim3(SEQ / 128, NHEAD, BATCH), 128, ASM_TOTAL>>>(Qh, Kh, Vh, Ch);

    gemm_out<<<dim3(DMODEL / BN, MROWS / BM), 256, GSM_TOTAL>>>(Ch, wo, b_o, out);
}

// round 13
// speedup vs baseline: 1.1159x; 1.0030x over previous
#include <cuda_runtime.h>
#include <cuda_fp16.h>
#include <math_constants.h>
#include <cstdint>

// Problem constants
#define BATCH 4
#define SEQ   2048
#define DMODEL 1024
#define NHEAD 16
#define DK    64
#define MROWS (BATCH * SEQ)   // 8192

// ---------------------------------------------------------------------------
// Scratch (static __device__ arrays; no allocations allowed)
// ---------------------------------------------------------------------------
__device__ __half g_qx[MROWS * DMODEL];
__device__ __half g_kx[MROWS * DMODEL];
__device__ __half g_vx[MROWS * DMODEL];
__device__ __half g_wq[DMODEL * DMODEL];
__device__ __half g_wk[DMODEL * DMODEL];
__device__ __half g_wv[DMODEL * DMODEL];
__device__ __half g_wo[DMODEL * DMODEL];
__device__ __half g_Qh[MROWS * DMODEL];
__device__ __half g_Kh[MROWS * DMODEL];
__device__ __half g_Vh[MROWS * DMODEL];
__device__ __half g_Ch[MROWS * DMODEL];

// ---------------------------------------------------------------------------
// Helpers
// ---------------------------------------------------------------------------
__device__ __forceinline__ uint32_t smem_u32(const void* p) {
    uint32_t a;
    asm("{ .reg .u64 t; cvta.to.shared.u64 t, %1; cvt.u32.u64 %0, t; }" : "=r"(a) : "l"(p));
    return a;
}
__device__ __forceinline__ uint32_t pack_half2(float a, float b) {
    __half2 h = __floats2half2_rn(a, b);
    return *reinterpret_cast<uint32_t*>(&h);
}
__device__ __forceinline__ float ex2(float x) {
    float r;
    asm("ex2.approx.f32 %0, %1;" : "=f"(r) : "f"(x));
    return r;
}
__device__ __forceinline__ void cp16(uint32_t dst, const void* src) {
    asm volatile("cp.async.cg.shared.global [%0], [%1], 16;" :: "r"(dst), "l"(src));
}
#define CP_COMMIT() asm volatile("cp.async.commit_group;" ::: "memory")
#define CP_WAIT(n)  asm volatile("cp.async.wait_group %0;" :: "n"(n) : "memory")

__device__ __forceinline__ void ldsm4(uint32_t* r, uint32_t addr) {
    asm volatile("ldmatrix.sync.aligned.m8n8.x4.shared.b16 {%0,%1,%2,%3}, [%4];"
                 : "=r"(r[0]), "=r"(r[1]), "=r"(r[2]), "=r"(r[3]) : "r"(addr));
}
__device__ __forceinline__ void ldsm4t(uint32_t* r, uint32_t addr) {
    asm volatile("ldmatrix.sync.aligned.m8n8.x4.trans.shared.b16 {%0,%1,%2,%3}, [%4];"
                 : "=r"(r[0]), "=r"(r[1]), "=r"(r[2]), "=r"(r[3]) : "r"(addr));
}
__device__ __forceinline__ void mma16816(float* c, const uint32_t* a, uint32_t b0, uint32_t b1) {
    asm volatile(
        "mma.sync.aligned.m16n8k16.row.col.f32.f16.f16.f32 "
        "{%0,%1,%2,%3}, {%4,%5,%6,%7}, {%8,%9}, {%0,%1,%2,%3};"
        : "+f"(c[0]), "+f"(c[1]), "+f"(c[2]), "+f"(c[3])
        : "r"(a[0]), "r"(a[1]), "r"(a[2]), "r"(a[3]), "r"(b0), "r"(b1));
}

// ---------------------------------------------------------------------------
// fp32 -> fp16 conversion (fused over tensors via blockIdx.y)
// ---------------------------------------------------------------------------
struct CvtArgs { const float* s[4]; __half* d[4]; };

__global__ __launch_bounds__(256)
void cvt16m(CvtArgs a, int n4)
{
    const float* s = a.s[blockIdx.y];
    __half* d = a.d[blockIdx.y];
    int i0 = blockIdx.x * 512 + threadIdx.x;
    int i1 = i0 + 256;
    float4 v0 = *(const float4*)(s + (size_t)i0 * 4);
    float4 v1 = *(const float4*)(s + (size_t)i1 * 4);
    uint2 h0, h1;
    h0.x = pack_half2(v0.x, v0.y); h0.y = pack_half2(v0.z, v0.w);
    h1.x = pack_half2(v1.x, v1.y); h1.y = pack_half2(v1.z, v1.w);
    *(uint2*)(d + (size_t)i0 * 4) = h0;
    *(uint2*)(d + (size_t)i1 * 4) = h1;
}

// ---------------------------------------------------------------------------
// FP16 GEMM (NT): R8 tile config, now with __launch_bounds__(256, 2) to
// force 2 CTAs/SM (16 warps) — attacks the latency-bound 8-warp regime.
// ---------------------------------------------------------------------------
#define BM 128
#define BN 128
#define BK 64
#define KST 72
#define GSM_BUF (BM * KST)
#define GSM_TOTAL (4 * GSM_BUF * 2)

template<bool F16OUT>
__device__ __forceinline__
void gemm_body(const __half* __restrict__ A, const __half* __restrict__ W,
               const float* __restrict__ bias, void* __restrict__ Cout,
               int N, int K, float alpha, __half* sh, int bx, int by)
{
    __half* As[2] = { sh, sh + GSM_BUF };
    __half* Bs[2] = { sh + 2 * GSM_BUF, sh + 3 * GSM_BUF };

    const int tid  = threadIdx.x;
    const int lane = tid & 31;
    const int wid  = tid >> 5;
    const int wm   = wid >> 2;
    const int wn   = wid & 3;

    const __half* Ap = A + (size_t)(by * BM) * K;
    const __half* Wp = W + (size_t)(bx * BN) * K;

    float acc[4][4][4];
#pragma unroll
    for (int mt = 0; mt < 4; mt++)
#pragma unroll
        for (int nt = 0; nt < 4; nt++)
#pragma unroll
            for (int r = 0; r < 4; r++) acc[mt][nt][r] = 0.0f;

    const int nslab = K / BK;
    auto load_tile = [&](int slab, int buf) {
#pragma unroll
        for (int i = 0; i < 4; i++) {
            int id = tid + i * 256;
            int r = id >> 3, c = (id & 7) << 3;
            cp16(smem_u32(&As[buf][r * KST + c]), Ap + (size_t)r * K + slab * BK + c);
        }
#pragma unroll
        for (int i = 0; i < 4; i++) {
            int id = tid + i * 256;
            int r = id >> 3, c = (id & 7) << 3;
            cp16(smem_u32(&Bs[buf][r * KST + c]), Wp + (size_t)r * K + slab * BK + c);
        }
        CP_COMMIT();
    };

    load_tile(0, 0);
    load_tile(1, 1);

    for (int s = 0; s < nslab; s++) {
        const int buf = s & 1;
        if (s + 1 < nslab) CP_WAIT(1); else CP_WAIT(0);
        __syncthreads();

#pragma unroll
        for (int ks = 0; ks < 4; ks++) {
            uint32_t af[4][4], bq[2][4];
#pragma unroll
            for (int mt = 0; mt < 4; mt++) {
                int row = wm * 64 + mt * 16 + (lane & 15);
                int col = ks * 16 + (lane >> 4) * 8;
                ldsm4(af[mt], smem_u32(&As[buf][row * KST + col]));
            }
#pragma unroll
            for (int ntp = 0; ntp < 2; ntp++) {
                int row = wn * 32 + ntp * 16 + (lane & 15);
                int col = ks * 16 + (lane >> 4) * 8;
                ldsm4(bq[ntp], smem_u32(&Bs[buf][row * KST + col]));
            }
#pragma unroll
            for (int mt = 0; mt < 4; mt++)
#pragma unroll
                for (int ntp = 0; ntp < 2; ntp++) {
                    mma16816(acc[mt][ntp * 2],     af[mt], bq[ntp][0], bq[ntp][2]);
                    mma16816(acc[mt][ntp * 2 + 1], af[mt], bq[ntp][1], bq[ntp][3]);
                }
        }
        __syncthreads();
        if (s + 2 < nslab) load_tile(s + 2, buf);
    }

    const int rA = lane >> 2, cA = lane & 3;
#pragma unroll
    for (int mt = 0; mt < 4; mt++) {
        int row = by * BM + wm * 64 + mt * 16 + rA;
#pragma unroll
        for (int nt = 0; nt < 4; nt++) {
            int col = bx * BN + wn * 32 + nt * 8 + 2 * cA;
            if (F16OUT) {
                __half* C = (__half*)Cout;
                *(uint32_t*)&C[(size_t)row * N + col] =
                    pack_half2(acc[mt][nt][0] * alpha, acc[mt][nt][1] * alpha);
                *(uint32_t*)&C[(size_t)(row + 8) * N + col] =
                    pack_half2(acc[mt][nt][2] * alpha, acc[mt][nt][3] * alpha);
            } else {
                float* C = (float*)Cout;
                float b0 = bias ? bias[col] : 0.0f;
                float b1 = bias ? bias[col + 1] : 0.0f;
                float2 v0 = { acc[mt][nt][0] + b0, acc[mt][nt][1] + b1 };
                float2 v1 = { acc[mt][nt][2] + b0, acc[mt][nt][3] + b1 };
                *(float2*)&C[(size_t)row * N + col]       = v0;
                *(float2*)&C[(size_t)(row + 8) * N + col] = v1;
            }
        }
    }
}

struct QKVArgs {
    const __half* A[3];
    const __half* W[3];
    __half* C[3];
    float alpha[3];
};

__global__ __launch_bounds__(256, 2)
void gemm_qkv(QKVArgs args)
{
    extern __shared__ __half sh[];
    int z = blockIdx.z;
    gemm_body<true>(args.A[z], args.W[z], nullptr, args.C[z],
                    DMODEL, DMODEL, args.alpha[z], sh, blockIdx.x, blockIdx.y);
}

__global__ __launch_bounds__(256, 2)
void gemm_out(const __half* __restrict__ A, const __half* __restrict__ W,
              const float* __restrict__ bias, float* __restrict__ C)
{
    extern __shared__ __half sh[];
    gemm_body<false>(A, W, bias, C, DMODEL, DMODEL, 1.0f, sh, blockIdx.x, blockIdx.y);
}

// ---------------------------------------------------------------------------
// Flash attention v3.1 (unchanged from R11 — at its structural limit).
// ---------------------------------------------------------------------------
#define AST 72
#define NKT (SEQ / 64)   // 32

#define ASM_Q  0
#define ASM_K0 (128 * AST)
#define ASM_K1 (ASM_K0 + 64 * AST)
#define ASM_V0 (ASM_K1 + 64 * AST)
#define ASM_V1 (ASM_V0 + 64 * AST)
#define ASM_TOTAL ((ASM_V1 + 64 * AST) * 2)   // 55296 bytes

__global__ __launch_bounds__(128)
void attn_f16(const __half* __restrict__ Q, const __half* __restrict__ Kg,
              const __half* __restrict__ Vg, __half* __restrict__ O)
{
    extern __shared__ __half sh[];
    __half* Qs = sh + ASM_Q;
    __half* Ks[2] = { sh + ASM_K0, sh + ASM_K1 };
    __half* Vs[2] = { sh + ASM_V0, sh + ASM_V1 };

    const int tid  = threadIdx.x;
    const int lane = tid & 31;
    const int wrp  = tid >> 5;
    const int rA   = lane >> 2;
    const int cA   = lane & 3;
    const int b  = blockIdx.z;
    const int h  = blockIdx.y;
    const int q0 = blockIdx.x * 128;

    const __half* Qg = Q  + (size_t)(b * SEQ + q0) * DMODEL + h * DK;
    const __half* Kp = Kg + (size_t)(b * SEQ) * DMODEL + h * DK;
    const __half* Vp = Vg + (size_t)(b * SEQ) * DMODEL + h * DK;

    auto load_kv = [&](int t, int buf) {
#pragma unroll
        for (int i = 0; i < 4; i++) {
            int id = tid + i * 128;
            int r = id >> 3, c = (id & 7) << 3;
            cp16(smem_u32(&Ks[buf][r * AST + c]), Kp + (size_t)(t * 64 + r) * DMODEL + c);
        }
#pragma unroll
        for (int i = 0; i < 4; i++) {
            int id = tid + i * 128;
            int r = id >> 3, c = (id & 7) << 3;
            cp16(smem_u32(&Vs[buf][r * AST + c]), Vp + (size_t)(t * 64 + r) * DMODEL + c);
        }
        CP_COMMIT();
    };

    load_kv(0, 0);

#pragma unroll
    for (int i = 0; i < 8; i++) {
        int id = tid + i * 128;
        int r = id >> 3, c = (id & 7) << 3;
        *(uint4*)&Qs[r * AST + c] = *(const uint4*)(Qg + (size_t)r * DMODEL + c);
    }
    __syncthreads();

    uint32_t qf[2][4][4];
#pragma unroll
    for (int mh = 0; mh < 2; mh++)
#pragma unroll
        for (int ks = 0; ks < 4; ks++) {
            int row = wrp * 32 + mh * 16 + (lane & 15);
            int col = ks * 16 + (lane >> 4) * 8;
            ldsm4(qf[mh][ks], smem_u32(&Qs[row * AST + col]));
        }

    float of[2][8][4];
#pragma unroll
    for (int mh = 0; mh < 2; mh++)
#pragma unroll
        for (int nt = 0; nt < 8; nt++)
#pragma unroll
            for (int r = 0; r < 4; r++) of[mh][nt][r] = 0.0f;
    float mrun[2][2] = {{-CUDART_INF_F, -CUDART_INF_F}, {-CUDART_INF_F, -CUDART_INF_F}};
    float lrun[2][2] = {{0.0f, 0.0f}, {0.0f, 0.0f}};

    for (int t = 0; t < NKT; t++) {
        const int buf = t & 1;
        CP_WAIT(0);
        __syncthreads();
        if (t + 1 < NKT) load_kv(t + 1, buf ^ 1);

        float sc[2][8][4];
#pragma unroll
        for (int mh = 0; mh < 2; mh++)
#pragma unroll
            for (int nt = 0; nt < 8; nt++)
#pragma unroll
                for (int r = 0; r < 4; r++) sc[mh][nt][r] = 0.0f;
#pragma unroll
        for (int ks = 0; ks < 4; ks++) {
#pragma unroll
            for (int ntp = 0; ntp < 4; ntp++) {
                uint32_t kb[4];
                int row = ntp * 16 + (lane & 15);
                int col = ks * 16 + (lane >> 4) * 8;
                ldsm4(kb, smem_u32(&Ks[buf][row * AST + col]));
                mma16816(sc[0][ntp * 2],     qf[0][ks], kb[0], kb[2]);
                mma16816(sc[0][ntp * 2 + 1], qf[0][ks], kb[1], kb[3]);
                mma16816(sc[1][ntp * 2],     qf[1][ks], kb[0], kb[2]);
                mma16816(sc[1][ntp * 2 + 1], qf[1][ks], kb[1], kb[3]);
            }
        }

        uint32_t pf[2][4][4];
#pragma unroll
        for (int mh = 0; mh < 2; mh++) {
            float mx0 = -CUDART_INF_F, mx1 = -CUDART_INF_F;
#pragma unroll
            for (int nt = 0; nt < 8; nt++) {
                mx0 = fmaxf(mx0, fmaxf(sc[mh][nt][0], sc[mh][nt][1]));
                mx1 = fmaxf(mx1, fmaxf(sc[mh][nt][2], sc[mh][nt][3]));
            }
            mx0 = fmaxf(mx0, __shfl_xor_sync(0xffffffffu, mx0, 1));
            mx0 = fmaxf(mx0, __shfl_xor_sync(0xffffffffu, mx0, 2));
            mx1 = fmaxf(mx1, __shfl_xor_sync(0xffffffffu, mx1, 1));
            mx1 = fmaxf(mx1, __shfl_xor_sync(0xffffffffu, mx1, 2));

            float nm0 = fmaxf(mrun[mh][0], mx0), nm1 = fmaxf(mrun[mh][1], mx1);
            float corr0 = ex2(mrun[mh][0] - nm0), corr1 = ex2(mrun[mh][1] - nm1);
            float s0 = 0.0f, s1 = 0.0f;
#pragma unroll
            for (int nt = 0; nt < 8; nt++) {
                float p0 = ex2(sc[mh][nt][0] - nm0);
                float p1 = ex2(sc[mh][nt][1] - nm0);
                float p2 = ex2(sc[mh][nt][2] - nm1);
                float p3 = ex2(sc[mh][nt][3] - nm1);
                s0 += p0 + p1; s1 += p2 + p3;
                pf[mh][nt >> 1][(nt & 1) * 2]     = pack_half2(p0, p1);
                pf[mh][nt >> 1][(nt & 1) * 2 + 1] = pack_half2(p2, p3);
            }
            lrun[mh][0] = lrun[mh][0] * corr0 + s0;
            lrun[mh][1] = lrun[mh][1] * corr1 + s1;
            mrun[mh][0] = nm0; mrun[mh][1] = nm1;
#pragma unroll
            for (int nt = 0; nt < 8; nt++) {
                of[mh][nt][0] *= corr0; of[mh][nt][1] *= corr0;
                of[mh][nt][2] *= corr1; of[mh][nt][3] *= corr1;
            }
        }

#pragma unroll
        for (int ks = 0; ks < 4; ks++) {
#pragma unroll
            for (int ntp = 0; ntp < 4; ntp++) {
                uint32_t vb[4];
                int vrow = ks * 16 + (lane & 15);
                int vcol = ntp * 16 + (lane >> 4) * 8;
                ldsm4t(vb, smem_u32(&Vs[buf][vrow * AST + vcol]));
                mma16816(of[0][ntp * 2],     pf[0][ks], vb[0], vb[1]);
                mma16816(of[0][ntp * 2 + 1], pf[0][ks], vb[2], vb[3]);
                mma16816(of[1][ntp * 2],     pf[1][ks], vb[0], vb[1]);
                mma16816(of[1][ntp * 2 + 1], pf[1][ks], vb[2], vb[3]);
            }
        }
    }

#pragma unroll
    for (int mh = 0; mh < 2; mh++) {
        float l0 = lrun[mh][0], l1 = lrun[mh][1];
        l0 += __shfl_xor_sync(0xffffffffu, l0, 1);
        l0 += __shfl_xor_sync(0xffffffffu, l0, 2);
        l1 += __shfl_xor_sync(0xffffffffu, l1, 1);
        l1 += __shfl_xor_sync(0xffffffffu, l1, 2);
        float inv0 = 1.0f / l0, inv1 = 1.0f / l1;
        __half* Op = O + (size_t)(b * SEQ + q0 + wrp * 32 + mh * 16) * DMODEL + h * DK;
#pragma unroll
        for (int nt = 0; nt < 8; nt++) {
            int col = nt * 8 + 2 * cA;
            *(uint32_t*)&Op[(size_t)rA * DMODEL + col] =
                pack_half2(of[mh][nt][0] * inv0, of[mh][nt][1] * inv0);
            *(uint32_t*)&Op[(size_t)(rA + 8) * DMODEL + col] =
                pack_half2(of[mh][nt][2] * inv1, of[mh][nt][3] * inv1);
        }
    }
}

// ---------------------------------------------------------------------------
// Launch
// ---------------------------------------------------------------------------
extern "C" void kernel_launch(void* const* d_in, const int* in_sizes, int n_in,
                              void* d_out, int out_size)
{
    const float* query = (const float*)d_in[0];
    const float* key_  = (const float*)d_in[1];
    const float* value = (const float*)d_in[2];
    const float* w_q   = (const float*)d_in[3];
    const float* w_k   = (const float*)d_in[4];
    const float* w_v   = (const float*)d_in[5];
    const float* w_o   = (const float*)d_in[6];
    const float* b_o   = (const float*)d_in[7];
    float* out = (float*)d_out;

    __half *qx, *kx, *vx, *wq, *wk, *wv, *wo, *Qh, *Kh, *Vh, *Ch;
    cudaGetSymbolAddress((void**)&qx, g_qx);
    cudaGetSymbolAddress((void**)&kx, g_kx);
    cudaGetSymbolAddress((void**)&vx, g_vx);
    cudaGetSymbolAddress((void**)&wq, g_wq);
    cudaGetSymbolAddress((void**)&wk, g_wk);
    cudaGetSymbolAddress((void**)&wv, g_wv);
    cudaGetSymbolAddress((void**)&wo, g_wo);
    cudaGetSymbolAddress((void**)&Qh, g_Qh);
    cudaGetSymbolAddress((void**)&Kh, g_Kh);
    cudaGetSymbolAddress((void**)&Vh, g_Vh);
    cudaGetSymbolAddress((void**)&Ch, g_Ch);

    const int NIN = MROWS * DMODEL / 4;
    const int NW  = DMODEL * DMODEL / 4;
    CvtArgs ia = {{query, key_, value, nullptr}, {qx, kx, vx, nullptr}};
    CvtArgs wa = {{w_q, w_k, w_v, w_o}, {wq, wk, wv, wo}};
    cvt16m<<<dim3(NIN / 512, 3), 256>>>(ia, NIN);
    cvt16m<<<dim3(NW / 512, 4), 256>>>(wa, NW);

    cudaFuncSetAttribute(gemm_qkv, cudaFuncAttributeMaxDynamicSharedMemorySize, GSM_TOTAL);
    cudaFuncSetAttribute(gemm_out, cudaFuncAttributeMaxDynamicSharedMemorySize, GSM_TOTAL);
    cudaFuncSetAttribute(attn_f16, cudaFuncAttributeMaxDynamicSharedMemorySize, ASM_TOTAL);

    QKVArgs qa;
    qa.A[0] = qx; qa.A[1] = kx; qa.A[2] = vx;
    qa.W[0] = wq; qa.W[1] = wk; qa.W[2] = wv;
    qa.C[0] = Qh; qa.C[1] = Kh; qa.C[2] = Vh;
    qa.alpha[0] = 0.125f * 1.44269504088896341f; qa.alpha[1] = 1.0f; qa.alpha[2] = 1.0f;
    gemm_qkv<<<dim3(DMODEL / BN, MROWS / BM, 3), 256, GSM_TOTAL>>>(qa);

    attn_f16<<<dim3(SEQ / 128, NHEAD, BATCH), 128, ASM_TOTAL>>>(Qh, Kh, Vh, Ch);

    gemm_out<<<dim3(DMODEL / BN, MROWS / BM), 256, GSM_TOTAL>>>(Ch, wo, b_o, out);
}

// round 14
// speedup vs baseline: 1.1410x; 1.0225x over previous
#include <cuda_runtime.h>
#include <cuda_fp16.h>
#include <math_constants.h>
#include <cstdint>

// Problem constants
#define BATCH 4
#define SEQ   2048
#define DMODEL 1024
#define NHEAD 16
#define DK    64
#define MROWS (BATCH * SEQ)   // 8192

// ---------------------------------------------------------------------------
// Scratch (static __device__ arrays; no allocations allowed)
// ---------------------------------------------------------------------------
__device__ __half g_qx[MROWS * DMODEL];
__device__ __half g_kx[MROWS * DMODEL];
__device__ __half g_vx[MROWS * DMODEL];
__device__ __half g_wq[DMODEL * DMODEL];
__device__ __half g_wk[DMODEL * DMODEL];
__device__ __half g_wv[DMODEL * DMODEL];
__device__ __half g_wo[DMODEL * DMODEL];
__device__ __half g_Qh[MROWS * DMODEL];
__device__ __half g_Kh[MROWS * DMODEL];
__device__ __half g_Vh[MROWS * DMODEL];
__device__ __half g_Ch[MROWS * DMODEL];

// ---------------------------------------------------------------------------
// Helpers
// ---------------------------------------------------------------------------
__device__ __forceinline__ uint32_t smem_u32(const void* p) {
    uint32_t a;
    asm("{ .reg .u64 t; cvta.to.shared.u64 t, %1; cvt.u32.u64 %0, t; }" : "=r"(a) : "l"(p));
    return a;
}
__device__ __forceinline__ uint32_t pack_half2(float a, float b) {
    __half2 h = __floats2half2_rn(a, b);
    return *reinterpret_cast<uint32_t*>(&h);
}
__device__ __forceinline__ float ex2(float x) {
    float r;
    asm("ex2.approx.f32 %0, %1;" : "=f"(r) : "f"(x));
    return r;
}
__device__ __forceinline__ void cp16(uint32_t dst, const void* src) {
    asm volatile("cp.async.cg.shared.global [%0], [%1], 16;" :: "r"(dst), "l"(src));
}
#define CP_COMMIT() asm volatile("cp.async.commit_group;" ::: "memory")
#define CP_WAIT(n)  asm volatile("cp.async.wait_group %0;" :: "n"(n) : "memory")

__device__ __forceinline__ void ldsm4(uint32_t* r, uint32_t addr) {
    asm volatile("ldmatrix.sync.aligned.m8n8.x4.shared.b16 {%0,%1,%2,%3}, [%4];"
                 : "=r"(r[0]), "=r"(r[1]), "=r"(r[2]), "=r"(r[3]) : "r"(addr));
}
__device__ __forceinline__ void ldsm4t(uint32_t* r, uint32_t addr) {
    asm volatile("ldmatrix.sync.aligned.m8n8.x4.trans.shared.b16 {%0,%1,%2,%3}, [%4];"
                 : "=r"(r[0]), "=r"(r[1]), "=r"(r[2]), "=r"(r[3]) : "r"(addr));
}
__device__ __forceinline__ void mma16816(float* c, const uint32_t* a, uint32_t b0, uint32_t b1) {
    asm volatile(
        "mma.sync.aligned.m16n8k16.row.col.f32.f16.f16.f32 "
        "{%0,%1,%2,%3}, {%4,%5,%6,%7}, {%8,%9}, {%0,%1,%2,%3};"
        : "+f"(c[0]), "+f"(c[1]), "+f"(c[2]), "+f"(c[3])
        : "r"(a[0]), "r"(a[1]), "r"(a[2]), "r"(a[3]), "r"(b0), "r"(b1));
}

// ---------------------------------------------------------------------------
// fp32 -> fp16 conversion (fused over tensors via blockIdx.y)
// ---------------------------------------------------------------------------
struct CvtArgs { const float* s[4]; __half* d[4]; };

__global__ __launch_bounds__(256)
void cvt16m(CvtArgs a, int n4)
{
    const float* s = a.s[blockIdx.y];
    __half* d = a.d[blockIdx.y];
    int i0 = blockIdx.x * 512 + threadIdx.x;
    int i1 = i0 + 256;
    float4 v0 = *(const float4*)(s + (size_t)i0 * 4);
    float4 v1 = *(const float4*)(s + (size_t)i1 * 4);
    uint2 h0, h1;
    h0.x = pack_half2(v0.x, v0.y); h0.y = pack_half2(v0.z, v0.w);
    h1.x = pack_half2(v1.x, v1.y); h1.y = pack_half2(v1.z, v1.w);
    *(uint2*)(d + (size_t)i0 * 4) = h0;
    *(uint2*)(d + (size_t)i1 * 4) = h1;
}

// ---------------------------------------------------------------------------
// FP16 GEMM (NT): R8 tile config, upgraded to a 3-stage cp.async pipeline:
// ONE __syncthreads per K-slab; loads issued before compute; each tile gets
// ~2 slab-computes of latency cover. SMEM 110.6KB/CTA -> still 2 CTAs/SM.
// ---------------------------------------------------------------------------
#define BM 128
#define BN 128
#define BK 64
#define KST 72
#define GSTG (2 * BM * KST)               // halves per stage (A+B) = 18432
#define GSM_TOTAL (3 * GSTG * 2)          // bytes = 110592

template<bool F16OUT>
__device__ __forceinline__
void gemm_body(const __half* __restrict__ A, const __half* __restrict__ W,
               const float* __restrict__ bias, void* __restrict__ Cout,
               int N, int K, float alpha, __half* sh, int bx, int by)
{
    const int tid  = threadIdx.x;
    const int lane = tid & 31;
    const int wid  = tid >> 5;
    const int wm   = wid >> 2;
    const int wn   = wid & 3;

    const __half* Ap = A + (size_t)(by * BM) * K;
    const __half* Wp = W + (size_t)(bx * BN) * K;

    float acc[4][4][4];
#pragma unroll
    for (int mt = 0; mt < 4; mt++)
#pragma unroll
        for (int nt = 0; nt < 4; nt++)
#pragma unroll
            for (int r = 0; r < 4; r++) acc[mt][nt][r] = 0.0f;

    const int nslab = K / BK;   // 16
    auto load_tile = [&](int slab, int st) {
        __half* As = sh + st * GSTG;
        __half* Bs = As + BM * KST;
#pragma unroll
        for (int i = 0; i < 4; i++) {
            int id = tid + i * 256;
            int r = id >> 3, c = (id & 7) << 3;
            cp16(smem_u32(&As[r * KST + c]), Ap + (size_t)r * K + slab * BK + c);
        }
#pragma unroll
        for (int i = 0; i < 4; i++) {
            int id = tid + i * 256;
            int r = id >> 3, c = (id & 7) << 3;
            cp16(smem_u32(&Bs[r * KST + c]), Wp + (size_t)r * K + slab * BK + c);
        }
        CP_COMMIT();
    };

    load_tile(0, 0);
    load_tile(1, 1);

    for (int s = 0; s < nslab; s++) {
        const int st = s % 3;
        // pending: tiles s, s+1 (if present). Ensure tile s landed.
        if (s + 1 < nslab) CP_WAIT(1); else CP_WAIT(0);
        __syncthreads();   // single barrier: data visibility + stage (s+2)%3 free
        if (s + 2 < nslab) load_tile(s + 2, (s + 2) % 3);

        __half* As = sh + st * GSTG;
        __half* Bs = As + BM * KST;
#pragma unroll
        for (int ks = 0; ks < 4; ks++) {
            uint32_t af[4][4], bq[2][4];
#pragma unroll
            for (int mt = 0; mt < 4; mt++) {
                int row = wm * 64 + mt * 16 + (lane & 15);
                int col = ks * 16 + (lane >> 4) * 8;
                ldsm4(af[mt], smem_u32(&As[row * KST + col]));
            }
#pragma unroll
            for (int ntp = 0; ntp < 2; ntp++) {
                int row = wn * 32 + ntp * 16 + (lane & 15);
                int col = ks * 16 + (lane >> 4) * 8;
                ldsm4(bq[ntp], smem_u32(&Bs[row * KST + col]));
            }
#pragma unroll
            for (int mt = 0; mt < 4; mt++)
#pragma unroll
                for (int ntp = 0; ntp < 2; ntp++) {
                    mma16816(acc[mt][ntp * 2],     af[mt], bq[ntp][0], bq[ntp][2]);
                    mma16816(acc[mt][ntp * 2 + 1], af[mt], bq[ntp][1], bq[ntp][3]);
                }
        }
    }

    const int rA = lane >> 2, cA = lane & 3;
#pragma unroll
    for (int mt = 0; mt < 4; mt++) {
        int row = by * BM + wm * 64 + mt * 16 + rA;
#pragma unroll
        for (int nt = 0; nt < 4; nt++) {
            int col = bx * BN + wn * 32 + nt * 8 + 2 * cA;
            if (F16OUT) {
                __half* C = (__half*)Cout;
                *(uint32_t*)&C[(size_t)row * N + col] =
                    pack_half2(acc[mt][nt][0] * alpha, acc[mt][nt][1] * alpha);
                *(uint32_t*)&C[(size_t)(row + 8) * N + col] =
                    pack_half2(acc[mt][nt][2] * alpha, acc[mt][nt][3] * alpha);
            } else {
                float* C = (float*)Cout;
                float b0 = bias ? bias[col] : 0.0f;
                float b1 = bias ? bias[col + 1] : 0.0f;
                float2 v0 = { acc[mt][nt][0] + b0, acc[mt][nt][1] + b1 };
                float2 v1 = { acc[mt][nt][2] + b0, acc[mt][nt][3] + b1 };
                *(float2*)&C[(size_t)row * N + col]       = v0;
                *(float2*)&C[(size_t)(row + 8) * N + col] = v1;
            }
        }
    }
}

struct QKVArgs {
    const __half* A[3];
    const __half* W[3];
    __half* C[3];
    float alpha[3];
};

__global__ __launch_bounds__(256, 2)
void gemm_qkv(QKVArgs args)
{
    extern __shared__ __half sh[];
    int z = blockIdx.z;
    gemm_body<true>(args.A[z], args.W[z], nullptr, args.C[z],
                    DMODEL, DMODEL, args.alpha[z], sh, blockIdx.x, blockIdx.y);
}

__global__ __launch_bounds__(256, 2)
void gemm_out(const __half* __restrict__ A, const __half* __restrict__ W,
              const float* __restrict__ bias, float* __restrict__ C)
{
    extern __shared__ __half sh[];
    gemm_body<false>(A, W, bias, C, DMODEL, DMODEL, 1.0f, sh, blockIdx.x, blockIdx.y);
}

// ---------------------------------------------------------------------------
// Flash attention v3.1 (unchanged from R11 — at its structural limit).
// ---------------------------------------------------------------------------
#define AST 72
#define NKT (SEQ / 64)   // 32

#define ASM_Q  0
#define ASM_K0 (128 * AST)
#define ASM_K1 (ASM_K0 + 64 * AST)
#define ASM_V0 (ASM_K1 + 64 * AST)
#define ASM_V1 (ASM_V0 + 64 * AST)
#define ASM_TOTAL ((ASM_V1 + 64 * AST) * 2)   // 55296 bytes

__global__ __launch_bounds__(128)
void attn_f16(const __half* __restrict__ Q, const __half* __restrict__ Kg,
              const __half* __restrict__ Vg, __half* __restrict__ O)
{
    extern __shared__ __half sh[];
    __half* Qs = sh + ASM_Q;
    __half* Ks[2] = { sh + ASM_K0, sh + ASM_K1 };
    __half* Vs[2] = { sh + ASM_V0, sh + ASM_V1 };

    const int tid  = threadIdx.x;
    const int lane = tid & 31;
    const int wrp  = tid >> 5;
    const int rA   = lane >> 2;
    const int cA   = lane & 3;
    const int b  = blockIdx.z;
    const int h  = blockIdx.y;
    const int q0 = blockIdx.x * 128;

    const __half* Qg = Q  + (size_t)(b * SEQ + q0) * DMODEL + h * DK;
    const __half* Kp = Kg + (size_t)(b * SEQ) * DMODEL + h * DK;
    const __half* Vp = Vg + (size_t)(b * SEQ) * DMODEL + h * DK;

    auto load_kv = [&](int t, int buf) {
#pragma unroll
        for (int i = 0; i < 4; i++) {
            int id = tid + i * 128;
            int r = id >> 3, c = (id & 7) << 3;
            cp16(smem_u32(&Ks[buf][r * AST + c]), Kp + (size_t)(t * 64 + r) * DMODEL + c);
        }
#pragma unroll
        for (int i = 0; i < 4; i++) {
            int id = tid + i * 128;
            int r = id >> 3, c = (id & 7) << 3;
            cp16(smem_u32(&Vs[buf][r * AST + c]), Vp + (size_t)(t * 64 + r) * DMODEL + c);
        }
        CP_COMMIT();
    };

    load_kv(0, 0);

#pragma unroll
    for (int i = 0; i < 8; i++) {
        int id = tid + i * 128;
        int r = id >> 3, c = (id & 7) << 3;
        *(uint4*)&Qs[r * AST + c] = *(const uint4*)(Qg + (size_t)r * DMODEL + c);
    }
    __syncthreads();

    uint32_t qf[2][4][4];
#pragma unroll
    for (int mh = 0; mh < 2; mh++)
#pragma unroll
        for (int ks = 0; ks < 4; ks++) {
            int row = wrp * 32 + mh * 16 + (lane & 15);
            int col = ks * 16 + (lane >> 4) * 8;
            ldsm4(qf[mh][ks], smem_u32(&Qs[row * AST + col]));
        }

    float of[2][8][4];
#pragma unroll
    for (int mh = 0; mh < 2; mh++)
#pragma unroll
        for (int nt = 0; nt < 8; nt++)
#pragma unroll
            for (int r = 0; r < 4; r++) of[mh][nt][r] = 0.0f;
    float mrun[2][2] = {{-CUDART_INF_F, -CUDART_INF_F}, {-CUDART_INF_F, -CUDART_INF_F}};
    float lrun[2][2] = {{0.0f, 0.0f}, {0.0f, 0.0f}};

    for (int t = 0; t < NKT; t++) {
        const int buf = t & 1;
        CP_WAIT(0);
        __syncthreads();
        if (t + 1 < NKT) load_kv(t + 1, buf ^ 1);

        float sc[2][8][4];
#pragma unroll
        for (int mh = 0; mh < 2; mh++)
#pragma unroll
            for (int nt = 0; nt < 8; nt++)
#pragma unroll
                for (int r = 0; r < 4; r++) sc[mh][nt][r] = 0.0f;
#pragma unroll
        for (int ks = 0; ks < 4; ks++) {
#pragma unroll
            for (int ntp = 0; ntp < 4; ntp++) {
                uint32_t kb[4];
                int row = ntp * 16 + (lane & 15);
                int col = ks * 16 + (lane >> 4) * 8;
                ldsm4(kb, smem_u32(&Ks[buf][row * AST + col]));
                mma16816(sc[0][ntp * 2],     qf[0][ks], kb[0], kb[2]);
                mma16816(sc[0][ntp * 2 + 1], qf[0][ks], kb[1], kb[3]);
                mma16816(sc[1][ntp * 2],     qf[1][ks], kb[0], kb[2]);
                mma16816(sc[1][ntp * 2 + 1], qf[1][ks], kb[1], kb[3]);
            }
        }

        uint32_t pf[2][4][4];
#pragma unroll
        for (int mh = 0; mh < 2; mh++) {
            float mx0 = -CUDART_INF_F, mx1 = -CUDART_INF_F;
#pragma unroll
            for (int nt = 0; nt < 8; nt++) {
                mx0 = fmaxf(mx0, fmaxf(sc[mh][nt][0], sc[mh][nt][1]));
                mx1 = fmaxf(mx1, fmaxf(sc[mh][nt][2], sc[mh][nt][3]));
            }
            mx0 = fmaxf(mx0, __shfl_xor_sync(0xffffffffu, mx0, 1));
            mx0 = fmaxf(mx0, __shfl_xor_sync(0xffffffffu, mx0, 2));
            mx1 = fmaxf(mx1, __shfl_xor_sync(0xffffffffu, mx1, 1));
            mx1 = fmaxf(mx1, __shfl_xor_sync(0xffffffffu, mx1, 2));

            float nm0 = fmaxf(mrun[mh][0], mx0), nm1 = fmaxf(mrun[mh][1], mx1);
            float corr0 = ex2(mrun[mh][0] - nm0), corr1 = ex2(mrun[mh][1] - nm1);
            float s0 = 0.0f, s1 = 0.0f;
#pragma unroll
            for (int nt = 0; nt < 8; nt++) {
                float p0 = ex2(sc[mh][nt][0] - nm0);
                float p1 = ex2(sc[mh][nt][1] - nm0);
                float p2 = ex2(sc[mh][nt][2] - nm1);
                float p3 = ex2(sc[mh][nt][3] - nm1);
                s0 += p0 + p1; s1 += p2 + p3;
                pf[mh][nt >> 1][(nt & 1) * 2]     = pack_half2(p0, p1);
                pf[mh][nt >> 1][(nt & 1) * 2 + 1] = pack_half2(p2, p3);
            }
            lrun[mh][0] = lrun[mh][0] * corr0 + s0;
            lrun[mh][1] = lrun[mh][1] * corr1 + s1;
            mrun[mh][0] = nm0; mrun[mh][1] = nm1;
#pragma unroll
            for (int nt = 0; nt < 8; nt++) {
                of[mh][nt][0] *= corr0; of[mh][nt][1] *= corr0;
                of[mh][nt][2] *= corr1; of[mh][nt][3] *= corr1;
            }
        }

#pragma unroll
        for (int ks = 0; ks < 4; ks++) {
#pragma unroll
            for (int ntp = 0; ntp < 4; ntp++) {
                uint32_t vb[4];
                int vrow = ks * 16 + (lane & 15);
                int vcol = ntp * 16 + (lane >> 4) * 8;
                ldsm4t(vb, smem_u32(&Vs[buf][vrow * AST + vcol]));
                mma16816(of[0][ntp * 2],     pf[0][ks], vb[0], vb[1]);
                mma16816(of[0][ntp * 2 + 1], pf[0][ks], vb[2], vb[3]);
                mma16816(of[1][ntp * 2],     pf[1][ks], vb[0], vb[1]);
                mma16816(of[1][ntp * 2 + 1], pf[1][ks], vb[2], vb[3]);
            }
        }
    }

#pragma unroll
    for (int mh = 0; mh < 2; mh++) {
        float l0 = lrun[mh][0], l1 = lrun[mh][1];
        l0 += __shfl_xor_sync(0xffffffffu, l0, 1);
        l0 += __shfl_xor_sync(0xffffffffu, l0, 2);
        l1 += __shfl_xor_sync(0xffffffffu, l1, 1);
        l1 += __shfl_xor_sync(0xffffffffu, l1, 2);
        float inv0 = 1.0f / l0, inv1 = 1.0f / l1;
        __half* Op = O + (size_t)(b * SEQ + q0 + wrp * 32 + mh * 16) * DMODEL + h * DK;
#pragma unroll
        for (int nt = 0; nt < 8; nt++) {
            int col = nt * 8 + 2 * cA;
            *(uint32_t*)&Op[(size_t)rA * DMODEL + col] =
                pack_half2(of[mh][nt][0] * inv0, of[mh][nt][1] * inv0);
            *(uint32_t*)&Op[(size_t)(rA + 8) * DMODEL + col] =
                pack_half2(of[mh][nt][2] * inv1, of[mh][nt][3] * inv1);
        }
    }
}

// ---------------------------------------------------------------------------
// Launch
// ---------------------------------------------------------------------------
extern "C" void kernel_launch(void* const* d_in, const int* in_sizes, int n_in,
                              void* d_out, int out_size)
{
    const float* query = (const float*)d_in[0];
    const float* key_  = (const float*)d_in[1];
    const float* value = (const float*)d_in[2];
    const float* w_q   = (const float*)d_in[3];
    const float* w_k   = (const float*)d_in[4];
    const float* w_v   = (const float*)d_in[5];
    const float* w_o   = (const float*)d_in[6];
    const float* b_o   = (const float*)d_in[7];
    float* out = (float*)d_out;

    __half *qx, *kx, *vx, *wq, *wk, *wv, *wo, *Qh, *Kh, *Vh, *Ch;
    cudaGetSymbolAddress((void**)&qx, g_qx);
    cudaGetSymbolAddress((void**)&kx, g_kx);
    cudaGetSymbolAddress((void**)&vx, g_vx);
    cudaGetSymbolAddress((void**)&wq, g_wq);
    cudaGetSymbolAddress((void**)&wk, g_wk);
    cudaGetSymbolAddress((void**)&wv, g_wv);
    cudaGetSymbolAddress((void**)&wo, g_wo);
    cudaGetSymbolAddress((void**)&Qh, g_Qh);
    cudaGetSymbolAddress((void**)&Kh, g_Kh);
    cudaGetSymbolAddress((void**)&Vh, g_Vh);
    cudaGetSymbolAddress((void**)&Ch, g_Ch);

    const int NIN = MROWS * DMODEL / 4;
    const int NW  = DMODEL * DMODEL / 4;
    CvtArgs ia = {{query, key_, value, nullptr}, {qx, kx, vx, nullptr}};
    CvtArgs wa = {{w_q, w_k, w_v, w_o}, {wq, wk, wv, wo}};
    cvt16m<<<dim3(NIN / 512, 3), 256>>>(ia, NIN);
    cvt16m<<<dim3(NW / 512, 4), 256>>>(wa, NW);

    cudaFuncSetAttribute(gemm_qkv, cudaFuncAttributeMaxDynamicSharedMemorySize, GSM_TOTAL);
    cudaFuncSetAttribute(gemm_out, cudaFuncAttributeMaxDynamicSharedMemorySize, GSM_TOTAL);
    cudaFuncSetAttribute(attn_f16, cudaFuncAttributeMaxDynamicSharedMemorySize, ASM_TOTAL);

    QKVArgs qa;
    qa.A[0] = qx; qa.A[1] = kx; qa.A[2] = vx;
    qa.W[0] = wq; qa.W[1] = wk; qa.W[2] = wv;
    qa.C[0] = Qh; qa.C[1] = Kh; qa.C[2] = Vh;
    qa.alpha[0] = 0.125f * 1.44269504088896341f; qa.alpha[1] = 1.0f; qa.alpha[2] = 1.0f;
    gemm_qkv<<<dim3(DMODEL / BN, MROWS / BM, 3), 256, GSM_TOTAL>>>(qa);

    attn_f16<<<dim3(SEQ / 128, NHEAD, BATCH), 128, ASM_TOTAL>>>(Qh, Kh, Vh, Ch);

    gemm_out<<<dim3(DMODEL / BN, MROWS / BM), 256, GSM_TOTAL>>>(Ch, wo, b_o, out);
}